// round 1
// baseline (speedup 1.0000x reference)
#include <cuda_runtime.h>

#define NN   50000
#define NE   640000
#define HIDD 128
#define EF   16
#define DIN  273        // 2*HID + EF + 1
#define KPAD 288        // DIN padded to multiple of 16
#define TE   64         // edges (or nodes) per CTA
#define NT   256        // threads per CTA
#define LDA  68         // padded leading dim of transposed A tiles (floats)

// scratch: aggregated messages per node (zeroed by init kernel each launch)
__device__ float g_mi[(size_t)NN * HIDD];

__device__ __forceinline__ float siluf(float v) { return v / (1.f + __expf(-v)); }

// ---------------------------------------------------------------------------
// Shared GEMM building blocks: C[64 x 128] (+=) A_T[K x 64] * B[K x 128]
// A is stored transposed in smem with leading dim LDA; B staged 16 rows at a
// time from global (weights, L2-resident). 4x8 microtile per thread.
// ---------------------------------------------------------------------------
__device__ __forceinline__ void mm_accum(const float* __restrict__ As,
                                         const float* __restrict__ Bs,
                                         int ti, int tj, float c[4][8]) {
#pragma unroll
    for (int k = 0; k < 16; k++) {
        float4 a  = *(const float4*)(As + k * LDA + (ti << 2));
        float4 b0 = *(const float4*)(Bs + k * HIDD + (tj << 3));
        float4 b1 = *(const float4*)(Bs + k * HIDD + (tj << 3) + 4);
        float av[4] = {a.x, a.y, a.z, a.w};
        float bv[8] = {b0.x, b0.y, b0.z, b0.w, b1.x, b1.y, b1.z, b1.w};
#pragma unroll
        for (int i = 0; i < 4; i++)
#pragma unroll
            for (int j = 0; j < 8; j++)
                c[i][j] = fmaf(av[i], bv[j], c[i][j]);
    }
}

__device__ __forceinline__ void load_w16(float* sB, const float* __restrict__ W,
                                         int kt, int kvalid, int tid) {
#pragma unroll
    for (int t = 0; t < 2; t++) {
        int q  = tid + t * NT;              // 512 float4 slots total
        int r  = q >> 5;
        int c4 = (q & 31) << 2;
        int row = kt + r;
        float4 v = make_float4(0.f, 0.f, 0.f, 0.f);
        if (row < kvalid) v = *(const float4*)(W + (size_t)row * HIDD + c4);
        *(float4*)(sB + r * HIDD + c4) = v;
    }
}

__device__ __forceinline__ void run_gemm(const float* As, float* sB,
                                         const float* __restrict__ W,
                                         int K, int kvalid,
                                         int ti, int tj, int tid, float c[4][8]) {
#pragma unroll 1
    for (int kt = 0; kt < K; kt += 16) {
        load_w16(sB, W, kt, kvalid, tid);
        __syncthreads();
        mm_accum(As + kt * LDA, sB, ti, tj, c);
        __syncthreads();
    }
}

// ---------------------------------------------------------------------------
// Init: zero g_mi, x_out = x
// ---------------------------------------------------------------------------
__global__ void egnn_init_kernel(const float* __restrict__ x,
                                 float* __restrict__ x_out) {
    int i      = blockIdx.x * blockDim.x + threadIdx.x;
    int stride = gridDim.x * blockDim.x;
    for (int j = i; j < NN * HIDD; j += stride) g_mi[j] = 0.f;
    for (int j = i; j < NN * 3;   j += stride) x_out[j] = x[j];
}

// ---------------------------------------------------------------------------
// Edge kernel: fully fused edge-side pipeline for 64 edges per CTA.
//   edge_in = [h[dst] | h[src] | d_sq | edge_attr]      (273, padded to 288)
//   s   = silu(edge_in @ em_w1 + em_b1)
//   mij = s @ em_w2 + em_b2                              (kept in smem only)
//   eij = sigmoid(mij . ei_w + ei_b)
//   g_mi[dst] += mij * eij                               (atomic scatter)
//   u   = silu(mij @ xm_w1 + xm_b1)
//   gate= tanh(u . xm_w2);  x_out[dst] += rel_x/(sqrt(d_sq+1e-8)+1)*gate
// ---------------------------------------------------------------------------
__global__ void __launch_bounds__(NT, 1) egnn_edge_kernel(
    const float* __restrict__ h,     const float* __restrict__ x,
    const int*   __restrict__ eidx,  const float* __restrict__ eattr,
    const float* __restrict__ em_w1, const float* __restrict__ em_b1,
    const float* __restrict__ em_w2, const float* __restrict__ em_b2,
    const float* __restrict__ ei_w,  const float* __restrict__ ei_b,
    const float* __restrict__ xm_w1, const float* __restrict__ xm_b1,
    const float* __restrict__ xm_w2,
    float* __restrict__ x_out)
{
    extern __shared__ float sm[];
    float* sA   = sm;                      // KPAD * LDA   (A transposed / later mij)
    float* sS   = sA + KPAD * LDA;         // HIDD * LDA   (intermediate, transposed)
    float* sB   = sS + HIDD * LDA;         // 16 * HIDD    (weight chunk)
    float* sVec = sB + 16 * HIDD;          // 5 * HIDD     (b1,b2,ei_w,xb1,xw2)
    float* sDsq = sVec + 5 * HIDD;         // TE
    float* sEij = sDsq + TE;               // TE
    float* sRel = sEij + TE;               // TE * 3
    int*   sSrc = (int*)(sRel + TE * 3);   // TE
    int*   sDst = sSrc + TE;               // TE

    const int tid = threadIdx.x;
    const int e0  = blockIdx.x * TE;
    const int ti  = tid >> 4;   // edge group (4 edges)
    const int tj  = tid & 15;   // col group (8 cols)

    if (tid < HIDD) {
        sVec[tid]            = em_b1[tid];
        sVec[HIDD + tid]     = em_b2[tid];
        sVec[2 * HIDD + tid] = ei_w[tid];
        sVec[3 * HIDD + tid] = xm_b1[tid];
        sVec[4 * HIDD + tid] = xm_w2[tid];
    }
    if (tid < TE) {
        int e = e0 + tid;
        int s = eidx[e];
        int d = eidx[NE + e];
        sSrc[tid] = s; sDst[tid] = d;
        float rx = x[d * 3 + 0] - x[s * 3 + 0];
        float ry = x[d * 3 + 1] - x[s * 3 + 1];
        float rz = x[d * 3 + 2] - x[s * 3 + 2];
        float dsq = rx * rx + ry * ry + rz * rz;
        sRel[tid * 3 + 0] = rx; sRel[tid * 3 + 1] = ry; sRel[tid * 3 + 2] = rz;
        sDsq[tid] = dsq;
        sA[256 * LDA + tid] = dsq;          // row 256 of edge_in
    }
    __syncthreads();

    // gather h[dst] -> rows [0,128), h[src] -> rows [128,256)  (transposed)
    for (int q = tid; q < TE * (HIDD / 4); q += NT) {
        int e  = q >> 5;
        int k4 = (q & 31) << 2;
        float4 vd = *(const float4*)(h + (size_t)sDst[e] * HIDD + k4);
        sA[(k4 + 0) * LDA + e] = vd.x; sA[(k4 + 1) * LDA + e] = vd.y;
        sA[(k4 + 2) * LDA + e] = vd.z; sA[(k4 + 3) * LDA + e] = vd.w;
        float4 vs = *(const float4*)(h + (size_t)sSrc[e] * HIDD + k4);
        sA[(128 + k4 + 0) * LDA + e] = vs.x; sA[(128 + k4 + 1) * LDA + e] = vs.y;
        sA[(128 + k4 + 2) * LDA + e] = vs.z; sA[(128 + k4 + 3) * LDA + e] = vs.w;
    }
    // edge_attr -> rows [257,273)
    for (int q = tid; q < TE * (EF / 4); q += NT) {
        int e  = q >> 2;
        int f4 = (q & 3) << 2;
        float4 v = *(const float4*)(eattr + (size_t)(e0 + e) * EF + f4);
        sA[(257 + f4 + 0) * LDA + e] = v.x; sA[(257 + f4 + 1) * LDA + e] = v.y;
        sA[(257 + f4 + 2) * LDA + e] = v.z; sA[(257 + f4 + 3) * LDA + e] = v.w;
    }
    // zero pad rows [273,288)
    for (int q = tid; q < (KPAD - DIN) * TE; q += NT)
        sA[(DIN + q / TE) * LDA + (q % TE)] = 0.f;
    __syncthreads();

    float c[4][8];

    // ---- GEMM1: edge_in @ em_w1, silu -> sS (transposed) ----
#pragma unroll
    for (int i = 0; i < 4; i++)
#pragma unroll
        for (int j = 0; j < 8; j++) c[i][j] = 0.f;
    run_gemm(sA, sB, em_w1, KPAD, DIN, ti, tj, tid, c);
#pragma unroll
    for (int j = 0; j < 8; j++) {
        int col = (tj << 3) + j;
        float b = sVec[col];
#pragma unroll
        for (int i = 0; i < 4; i++)
            sS[col * LDA + (ti << 2) + i] = siluf(c[i][j] + b);
    }
    __syncthreads();

    // ---- GEMM2: s @ em_w2 + b2 = mij -> sA rows [0,128) (transposed) ----
#pragma unroll
    for (int i = 0; i < 4; i++)
#pragma unroll
        for (int j = 0; j < 8; j++) c[i][j] = 0.f;
    run_gemm(sS, sB, em_w2, HIDD, HIDD, ti, tj, tid, c);
#pragma unroll
    for (int j = 0; j < 8; j++) {
        int col = (tj << 3) + j;
        float b = sVec[HIDD + col];
#pragma unroll
        for (int i = 0; i < 4; i++)
            sA[col * LDA + (ti << 2) + i] = c[i][j] + b;
    }
    __syncthreads();

    // ---- eij = sigmoid(mij . ei_w + ei_b) ----
    if (tid < TE) {
        float acc = 0.f;
#pragma unroll 4
        for (int k = 0; k < HIDD; k++) acc += sA[k * LDA + tid] * sVec[2 * HIDD + k];
        acc += ei_b[0];
        sEij[tid] = 1.f / (1.f + __expf(-acc));
    }
    __syncthreads();

    // ---- scatter: g_mi[dst] += mij * eij (coalesced atomics) ----
    for (int q = tid; q < TE * HIDD; q += NT) {
        int e = q >> 7;
        int k = q & 127;
        atomicAdd(&g_mi[(size_t)sDst[e] * HIDD + k], sA[k * LDA + e] * sEij[e]);
    }

    // ---- GEMM3: u = silu(mij @ xm_w1 + xb1) -> sS ----
#pragma unroll
    for (int i = 0; i < 4; i++)
#pragma unroll
        for (int j = 0; j < 8; j++) c[i][j] = 0.f;
    run_gemm(sA, sB, xm_w1, HIDD, HIDD, ti, tj, tid, c);
#pragma unroll
    for (int j = 0; j < 8; j++) {
        int col = (tj << 3) + j;
        float b = sVec[3 * HIDD + col];
#pragma unroll
        for (int i = 0; i < 4; i++)
            sS[col * LDA + (ti << 2) + i] = siluf(c[i][j] + b);
    }
    __syncthreads();

    // ---- x gate + coordinate scatter ----
    if (tid < TE) {
        float acc = 0.f;
#pragma unroll 4
        for (int k = 0; k < HIDD; k++) acc += sS[k * LDA + tid] * sVec[4 * HIDD + k];
        float g    = tanhf(acc);
        float coef = g / (sqrtf(sDsq[tid] + 1e-8f) + 1.f);
        int d = sDst[tid];
        atomicAdd(&x_out[d * 3 + 0], sRel[tid * 3 + 0] * coef);
        atomicAdd(&x_out[d * 3 + 1], sRel[tid * 3 + 1] * coef);
        atomicAdd(&x_out[d * 3 + 2], sRel[tid * 3 + 2] * coef);
    }
}

// ---------------------------------------------------------------------------
// Node kernel: h_out = h + node_mlp(concat(mi, h)) for 64 nodes per CTA.
// ---------------------------------------------------------------------------
__global__ void __launch_bounds__(NT, 1) egnn_node_kernel(
    const float* __restrict__ h,
    const float* __restrict__ nm_w1, const float* __restrict__ nm_b1,
    const float* __restrict__ nm_w2, const float* __restrict__ nm_b2,
    float* __restrict__ h_out)
{
    extern __shared__ float sm[];
    float* sA   = sm;                    // 256 * LDA (concat(mi,h) transposed)
    float* sS   = sA + 256 * LDA;        // HIDD * LDA
    float* sB   = sS + HIDD * LDA;       // 16 * HIDD
    float* sVec = sB + 16 * HIDD;        // 2 * HIDD

    const int tid = threadIdx.x;
    const int n0  = blockIdx.x * TE;
    const int ti  = tid >> 4;
    const int tj  = tid & 15;

    if (tid < HIDD) { sVec[tid] = nm_b1[tid]; sVec[HIDD + tid] = nm_b2[tid]; }

    for (int q = tid; q < TE * (HIDD / 4); q += NT) {
        int e  = q >> 5;
        int k4 = (q & 31) << 2;
        int n  = n0 + e;
        float4 mv = make_float4(0.f, 0.f, 0.f, 0.f);
        float4 hv = make_float4(0.f, 0.f, 0.f, 0.f);
        if (n < NN) {
            mv = *(const float4*)(g_mi + (size_t)n * HIDD + k4);
            hv = *(const float4*)(h    + (size_t)n * HIDD + k4);
        }
        sA[(k4 + 0) * LDA + e] = mv.x; sA[(k4 + 1) * LDA + e] = mv.y;
        sA[(k4 + 2) * LDA + e] = mv.z; sA[(k4 + 3) * LDA + e] = mv.w;
        sA[(128 + k4 + 0) * LDA + e] = hv.x; sA[(128 + k4 + 1) * LDA + e] = hv.y;
        sA[(128 + k4 + 2) * LDA + e] = hv.z; sA[(128 + k4 + 3) * LDA + e] = hv.w;
    }
    __syncthreads();

    float c[4][8];
#pragma unroll
    for (int i = 0; i < 4; i++)
#pragma unroll
        for (int j = 0; j < 8; j++) c[i][j] = 0.f;
    run_gemm(sA, sB, nm_w1, 256, 256, ti, tj, tid, c);
#pragma unroll
    for (int j = 0; j < 8; j++) {
        int col = (tj << 3) + j;
        float b = sVec[col];
#pragma unroll
        for (int i = 0; i < 4; i++)
            sS[col * LDA + (ti << 2) + i] = siluf(c[i][j] + b);
    }
    __syncthreads();

#pragma unroll
    for (int i = 0; i < 4; i++)
#pragma unroll
        for (int j = 0; j < 8; j++) c[i][j] = 0.f;
    run_gemm(sS, sB, nm_w2, HIDD, HIDD, ti, tj, tid, c);
#pragma unroll
    for (int j = 0; j < 8; j++) {
        int col = (tj << 3) + j;
        float b = sVec[HIDD + col];
#pragma unroll
        for (int i = 0; i < 4; i++) {
            int e = (ti << 2) + i;
            int n = n0 + e;
            if (n < NN)
                h_out[(size_t)n * HIDD + col] = c[i][j] + b + sA[(128 + col) * LDA + e];
        }
    }
}

// ---------------------------------------------------------------------------

static const int EDGE_SMEM = (KPAD * LDA + HIDD * LDA + 16 * HIDD + 5 * HIDD
                              + TE + TE + TE * 3 + TE * 2) * 4;     // 125696 B
static const int NODE_SMEM = (256 * LDA + HIDD * LDA + 16 * HIDD + 2 * HIDD) * 4; // 113664 B

extern "C" void kernel_launch(void* const* d_in, const int* in_sizes, int n_in,
                              void* d_out, int out_size) {
    const float* h     = (const float*)d_in[0];
    const float* x     = (const float*)d_in[1];
    const int*   eidx  = (const int*)  d_in[2];
    const float* eattr = (const float*)d_in[3];
    const float* em_w1 = (const float*)d_in[4];
    const float* em_b1 = (const float*)d_in[5];
    const float* em_w2 = (const float*)d_in[6];
    const float* em_b2 = (const float*)d_in[7];
    const float* ei_w  = (const float*)d_in[8];
    const float* ei_b  = (const float*)d_in[9];
    const float* xm_w1 = (const float*)d_in[10];
    const float* xm_b1 = (const float*)d_in[11];
    const float* xm_w2 = (const float*)d_in[12];
    const float* nm_w1 = (const float*)d_in[13];
    const float* nm_b1 = (const float*)d_in[14];
    const float* nm_w2 = (const float*)d_in[15];
    const float* nm_b2 = (const float*)d_in[16];

    float* out   = (float*)d_out;
    float* h_out = out;                        // [NN, 128]
    float* x_out = out + (size_t)NN * HIDD;    // [NN, 3]

    cudaFuncSetAttribute(egnn_edge_kernel,
                         cudaFuncAttributeMaxDynamicSharedMemorySize, EDGE_SMEM);
    cudaFuncSetAttribute(egnn_node_kernel,
                         cudaFuncAttributeMaxDynamicSharedMemorySize, NODE_SMEM);

    egnn_init_kernel<<<2048, 256>>>(x, x_out);
    egnn_edge_kernel<<<NE / TE, NT, EDGE_SMEM>>>(
        h, x, eidx, eattr, em_w1, em_b1, em_w2, em_b2,
        ei_w, ei_b, xm_w1, xm_b1, xm_w2, x_out);
    egnn_node_kernel<<<(NN + TE - 1) / TE, NT, NODE_SMEM>>>(
        h, nm_w1, nm_b1, nm_w2, nm_b2, h_out);
}

// round 3
// speedup vs baseline: 3.2631x; 3.2631x over previous
#include <cuda_runtime.h>
#include <cuda_bf16.h>
#include <cstdint>

#define NN   50000
#define NE   640000
#define HIDD 128
#define EF   16
#define DIN  273
#define K1   288          // GEMM1 K padded
#define LD1  296          // padded row stride (elems) for K=288 tiles
#define LD2  136          // padded row stride for K=128 tiles
#define K3   256
#define LD3  264          // padded row stride for K=256 tiles
#define ME   128          // rows (edges/nodes) per CTA
#define NT   256          // 8 warps

// ---- misc smem offsets (bytes) ----
#define OFF_B1   0
#define OFF_B2   512
#define OFF_EIW  1024
#define OFF_XB1  1536
#define OFF_XW2  2048
#define OFF_DSQ  2560
#define OFF_EIJ  3072
#define OFF_RLX  3584
#define OFF_RLY  4096
#define OFF_RLZ  4608
#define OFF_DST  5120
#define OFF_SRC  5632
#define OFF_PART 6144      // fp32[256]
#define SA_OFF   8192                        // A1 [128][LD1] bf16 (75776 B)
#define SS_OFF   8192                        // S  [128][LD2] bf16 (34816 B, reuse)
#define SMM_OFF  (8192 + 34816)              // M  [128][LD2] bf16 (43008)
#define SW_OFF   (8192 + 128 * LD1 * 2)      // 83968: W1t [128][LD1]
#define SW2A_OFF SW_OFF                      // W2t  [128][LD2] (reuse)
#define SW2B_OFF (SW_OFF + 34816)            // XW1t [128][LD2]
#define EDGE_SMEM (SW_OFF + 128 * LD1 * 2)   // 159744

#define NA_OFF   8192                        // [128][LD3] (67584 B); S reuse
#define NW_OFF   (8192 + 128 * LD3 * 2)      // 75776: nw1t; nw2t reuse
#define NODE_SMEM (NW_OFF + 128 * LD3 * 2)   // 143360

__device__ float g_mi[(size_t)NN * HIDD];
__device__ __align__(16) __nv_bfloat16 g_w1t [128 * LD1];
__device__ __align__(16) __nv_bfloat16 g_w2t [128 * LD2];
__device__ __align__(16) __nv_bfloat16 g_xw1t[128 * LD2];
__device__ __align__(16) __nv_bfloat16 g_nw1t[128 * LD3];
__device__ __align__(16) __nv_bfloat16 g_nw2t[128 * LD2];

// ---------------------------------------------------------------------------
__device__ __forceinline__ uint32_t smem_u32(const void* p) {
    uint32_t a;
    asm("{ .reg .u64 t; cvta.to.shared.u64 t, %1; cvt.u32.u64 %0, t; }"
        : "=r"(a) : "l"(p));
    return a;
}
__device__ __forceinline__ uint32_t lds32(uint32_t a) {
    uint32_t v;
    asm volatile("ld.shared.b32 %0, [%1];" : "=r"(v) : "r"(a));
    return v;
}
__device__ __forceinline__ void sts32(uint32_t a, uint32_t v) {
    asm volatile("st.shared.b32 [%0], %1;" :: "r"(a), "r"(v));
}
__device__ __forceinline__ void sts128(uint32_t a, uint4 v) {
    asm volatile("st.shared.v4.b32 [%0], {%1,%2,%3,%4};"
                 :: "r"(a), "r"(v.x), "r"(v.y), "r"(v.z), "r"(v.w));
}
__device__ __forceinline__ uint32_t pk(float lo, float hi) {
    uint32_t l = __bfloat16_as_ushort(__float2bfloat16(lo));
    uint32_t h = __bfloat16_as_ushort(__float2bfloat16(hi));
    return l | (h << 16);
}
__device__ __forceinline__ float ubf_lo(uint32_t v) {
    return __bfloat162float(__ushort_as_bfloat16((unsigned short)(v & 0xFFFF)));
}
__device__ __forceinline__ float ubf_hi(uint32_t v) {
    return __bfloat162float(__ushort_as_bfloat16((unsigned short)(v >> 16)));
}
__device__ __forceinline__ float siluf(float v) { return v / (1.f + __expf(-v)); }

__device__ __forceinline__ void mma_bf16(float* c,
                                         uint32_t a0, uint32_t a1, uint32_t a2, uint32_t a3,
                                         uint32_t b0, uint32_t b1) {
    asm volatile("mma.sync.aligned.m16n8k16.row.col.f32.bf16.bf16.f32 "
                 "{%0,%1,%2,%3}, {%4,%5,%6,%7}, {%8,%9}, {%0,%1,%2,%3};"
                 : "+f"(c[0]), "+f"(c[1]), "+f"(c[2]), "+f"(c[3])
                 : "r"(a0), "r"(a1), "r"(a2), "r"(a3), "r"(b0), "r"(b1));
}

// C[128x128] += A[128xK] * Wt[128xK]^T ; warp tile 32(m) x 64(n).
// aBase/bBase: smem byte addr of (m0+gid, tig*2) / (n0+gid, tig*2).
__device__ __forceinline__ void warp_gemm(uint32_t aBase, uint32_t bBase,
                                          uint32_t ldRow, int ksteps,
                                          float c[2][8][4]) {
    const uint32_t r8 = 8u * ldRow;
#pragma unroll 2
    for (int ks = 0; ks < ksteps; ks++) {
        uint32_t aA = aBase + ks * 32;
        uint32_t a00 = lds32(aA),            a01 = lds32(aA + r8);
        uint32_t a02 = lds32(aA + 16),       a03 = lds32(aA + r8 + 16);
        uint32_t aB  = aA + 2 * r8;
        uint32_t a10 = lds32(aB),            a11 = lds32(aB + r8);
        uint32_t a12 = lds32(aB + 16),       a13 = lds32(aB + r8 + 16);
        uint32_t bb = bBase + ks * 32;
#pragma unroll
        for (int nt = 0; nt < 8; nt++) {
            uint32_t b0 = lds32(bb), b1 = lds32(bb + 16);
            mma_bf16(c[0][nt], a00, a01, a02, a03, b0, b1);
            mma_bf16(c[1][nt], a10, a11, a12, a13, b0, b1);
            bb += r8;
        }
    }
}

__device__ __forceinline__ void zero_c(float c[2][8][4]) {
#pragma unroll
    for (int i = 0; i < 2; i++)
#pragma unroll
        for (int j = 0; j < 8; j++)
#pragma unroll
            for (int k = 0; k < 4; k++) c[i][j][k] = 0.f;
}

// ---------------------------------------------------------------------------
__global__ void egnn_init_kernel(const float* __restrict__ x, float* __restrict__ x_out) {
    int i = blockIdx.x * blockDim.x + threadIdx.x;
    int s = gridDim.x * blockDim.x;
    for (int j = i; j < NN * HIDD; j += s) g_mi[j] = 0.f;
    for (int j = i; j < NN * 3;   j += s) x_out[j] = x[j];
}

// weights -> bf16, transposed to [n][k] row-major with padded stride
__global__ void egnn_prep_kernel(const float* __restrict__ em_w1, const float* __restrict__ em_w2,
                                 const float* __restrict__ xm_w1, const float* __restrict__ nm_w1,
                                 const float* __restrict__ nm_w2) {
    const int T1 = 128 * LD1;
    const int T2 = T1 + 128 * LD2;
    const int T3 = T2 + 128 * LD2;
    const int T4 = T3 + 128 * LD3;
    const int T5 = T4 + 128 * LD2;
    int i = blockIdx.x * blockDim.x + threadIdx.x;
    int s = gridDim.x * blockDim.x;
    for (int p = i; p < T5; p += s) {
        const float* W; __nv_bfloat16* dst; int kv, ld, pl = p;
        if (p < T1)      { W = em_w1; dst = g_w1t;  kv = DIN; ld = LD1; }
        else if (p < T2) { W = em_w2; dst = g_w2t;  kv = 128; ld = LD2; pl = p - T1; }
        else if (p < T3) { W = xm_w1; dst = g_xw1t; kv = 128; ld = LD2; pl = p - T2; }
        else if (p < T4) { W = nm_w1; dst = g_nw1t; kv = 256; ld = LD3; pl = p - T3; }
        else             { W = nm_w2; dst = g_nw2t; kv = 128; ld = LD2; pl = p - T4; }
        int n = pl / ld, k = pl % ld;
        float v = (k < kv) ? W[(size_t)k * 128 + n] : 0.f;
        dst[pl] = __float2bfloat16(v);
    }
}

// ---------------------------------------------------------------------------
// Edge kernel: 128 edges per CTA, HMMA pipeline.
// ---------------------------------------------------------------------------
__global__ void __launch_bounds__(NT, 1) egnn_edge_kernel(
    const float* __restrict__ h,     const float* __restrict__ x,
    const int*   __restrict__ eidx,  const float* __restrict__ eattr,
    const float* __restrict__ em_b1, const float* __restrict__ em_b2,
    const float* __restrict__ ei_w,  const float* __restrict__ ei_b,
    const float* __restrict__ xm_b1, const float* __restrict__ xm_w2,
    float* __restrict__ x_out)
{
    extern __shared__ unsigned char sm[];
    const uint32_t sb = smem_u32(sm);
    const int tid  = threadIdx.x;
    const int wid  = tid >> 5;
    const int lane = tid & 31;
    const int gid  = lane >> 2;
    const int tig  = lane & 3;
    const int m0   = (wid >> 1) * 32;
    const int n0   = (wid & 1) * 64;
    const int e0   = blockIdx.x * ME;

    float* sB1  = (float*)(sm + OFF_B1);
    float* sB2  = (float*)(sm + OFF_B2);
    float* sEIW = (float*)(sm + OFF_EIW);
    float* sXB1 = (float*)(sm + OFF_XB1);
    float* sXW2 = (float*)(sm + OFF_XW2);
    float* sDsq = (float*)(sm + OFF_DSQ);
    float* sEij = (float*)(sm + OFF_EIJ);
    float* sRlX = (float*)(sm + OFF_RLX);
    float* sRlY = (float*)(sm + OFF_RLY);
    float* sRlZ = (float*)(sm + OFF_RLZ);
    int*   sDst = (int*)  (sm + OFF_DST);
    int*   sSrc = (int*)  (sm + OFF_SRC);
    float* sPart= (float*)(sm + OFF_PART);

    if (tid < 128) {
        sB1[tid]  = em_b1[tid]; sB2[tid] = em_b2[tid]; sEIW[tid] = ei_w[tid];
        sXB1[tid] = xm_b1[tid]; sXW2[tid] = xm_w2[tid];
        int e  = e0 + tid;
        int s_ = eidx[e], d_ = eidx[NE + e];
        sSrc[tid] = s_; sDst[tid] = d_;
        float rx = x[d_ * 3 + 0] - x[s_ * 3 + 0];
        float ry = x[d_ * 3 + 1] - x[s_ * 3 + 1];
        float rz = x[d_ * 3 + 2] - x[s_ * 3 + 2];
        sRlX[tid] = rx; sRlY[tid] = ry; sRlZ[tid] = rz;
        sDsq[tid] = rx * rx + ry * ry + rz * rz;
    }
    __syncthreads();

    // gather A1 rows (bf16): [h[dst] | h[src] | dsq | eattr | 0]
    for (int q = tid; q < ME * 36; q += NT) {
        int e = q / 36, ch = q % 36;
        uint4 w;
        int col;
        if (ch < 32) {
            int node = (ch < 16) ? sDst[e] : sSrc[e];
            col = (ch & 15) * 8 + ((ch < 16) ? 0 : 128);
            const float4* hp = (const float4*)(h + (size_t)node * HIDD + (ch & 15) * 8);
            float4 v0 = hp[0], v1 = hp[1];
            w.x = pk(v0.x, v0.y); w.y = pk(v0.z, v0.w);
            w.z = pk(v1.x, v1.y); w.w = pk(v1.z, v1.w);
        } else {
            col = 256 + (ch - 32) * 8;
            float v[8];
#pragma unroll
            for (int j = 0; j < 8; j++) {
                int idx = col + j - 256;
                float f = 0.f;
                if (idx == 0) f = sDsq[e];
                else if (idx <= EF) f = eattr[(size_t)(e0 + e) * EF + (idx - 1)];
                v[j] = f;
            }
            w.x = pk(v[0], v[1]); w.y = pk(v[2], v[3]);
            w.z = pk(v[4], v[5]); w.w = pk(v[6], v[7]);
        }
        sts128(sb + SA_OFF + (uint32_t)(e * LD1 + col) * 2, w);
    }
    // copy W1t
    {
        uint4* d = (uint4*)(sm + SW_OFF);
        const uint4* s = (const uint4*)g_w1t;
        for (int q = tid; q < 128 * LD1 * 2 / 16; q += NT) d[q] = s[q];
    }
    __syncthreads();

    float c[2][8][4];

    // ---- GEMM1: silu(A1 @ W1 + b1) -> S ----
    zero_c(c);
    warp_gemm(sb + SA_OFF + (uint32_t)((m0 + gid) * LD1 + tig * 2) * 2,
              sb + SW_OFF + (uint32_t)((n0 + gid) * LD1 + tig * 2) * 2,
              LD1 * 2, K1 / 16, c);
    __syncthreads();   // done reading A1/W1t

#pragma unroll
    for (int mt = 0; mt < 2; mt++)
#pragma unroll
        for (int nt = 0; nt < 8; nt++) {
            int row = m0 + mt * 16 + gid;
            int col = n0 + nt * 8 + tig * 2;
            float* cc = c[mt][nt];
            sts32(sb + SS_OFF + (uint32_t)(row * LD2 + col) * 2,
                  pk(siluf(cc[0] + sB1[col]), siluf(cc[1] + sB1[col + 1])));
            sts32(sb + SS_OFF + (uint32_t)((row + 8) * LD2 + col) * 2,
                  pk(siluf(cc[2] + sB1[col]), siluf(cc[3] + sB1[col + 1])));
        }
    // copy W2t + XW1t (over old W1t region)
    {
        uint4* d2 = (uint4*)(sm + SW2A_OFF);
        const uint4* s2 = (const uint4*)g_w2t;
        for (int q = tid; q < 128 * LD2 * 2 / 16; q += NT) d2[q] = s2[q];
        uint4* d3 = (uint4*)(sm + SW2B_OFF);
        const uint4* s3 = (const uint4*)g_xw1t;
        for (int q = tid; q < 128 * LD2 * 2 / 16; q += NT) d3[q] = s3[q];
    }
    __syncthreads();

    // ---- GEMM2: mij = S @ W2 + b2 -> M ; eij partial dot ----
    zero_c(c);
    warp_gemm(sb + SS_OFF  + (uint32_t)((m0 + gid) * LD2 + tig * 2) * 2,
              sb + SW2A_OFF + (uint32_t)((n0 + gid) * LD2 + tig * 2) * 2,
              LD2 * 2, 8, c);

    {
        float p[2][2] = {{0.f, 0.f}, {0.f, 0.f}};
#pragma unroll
        for (int mt = 0; mt < 2; mt++)
#pragma unroll
            for (int nt = 0; nt < 8; nt++) {
                int row = m0 + mt * 16 + gid;
                int col = n0 + nt * 8 + tig * 2;
                float* cc = c[mt][nt];
                float v0 = cc[0] + sB2[col], v1 = cc[1] + sB2[col + 1];
                float v2 = cc[2] + sB2[col], v3 = cc[3] + sB2[col + 1];
                sts32(sb + SMM_OFF + (uint32_t)(row * LD2 + col) * 2, pk(v0, v1));
                sts32(sb + SMM_OFF + (uint32_t)((row + 8) * LD2 + col) * 2, pk(v2, v3));
                p[mt][0] += v0 * sEIW[col] + v1 * sEIW[col + 1];
                p[mt][1] += v2 * sEIW[col] + v3 * sEIW[col + 1];
            }
#pragma unroll
        for (int mt = 0; mt < 2; mt++)
#pragma unroll
            for (int hh = 0; hh < 2; hh++) {
                float v = p[mt][hh];
                v += __shfl_xor_sync(0xffffffffu, v, 1);
                v += __shfl_xor_sync(0xffffffffu, v, 2);
                if (tig == 0)
                    sPart[(wid & 1) * 128 + m0 + mt * 16 + hh * 8 + gid] = v;
            }
    }
    __syncthreads();

    if (tid < 128) {
        float t = sPart[tid] + sPart[128 + tid] + ei_b[0];
        sEij[tid] = 1.f / (1.f + __expf(-t));
    }
    __syncthreads();

    // ---- scatter: g_mi[dst] += mij * eij  (vector reductions, fp32) ----
    for (int q = tid; q < ME * 32; q += NT) {
        int e = q >> 5, c4 = (q & 31) * 4;
        const uint32_t* mp = (const uint32_t*)(sm + SMM_OFF + (uint32_t)(e * LD2 + c4) * 2);
        uint32_t u0 = mp[0], u1 = mp[1];
        float ei = sEij[e];
        float v0 = ubf_lo(u0) * ei, v1 = ubf_hi(u0) * ei;
        float v2 = ubf_lo(u1) * ei, v3 = ubf_hi(u1) * ei;
        float* g = g_mi + (size_t)sDst[e] * HIDD + c4;
        asm volatile("red.global.add.v4.f32 [%0], {%1,%2,%3,%4};"
                     :: "l"(g), "f"(v0), "f"(v1), "f"(v2), "f"(v3) : "memory");
    }

    // ---- GEMM3: u = silu(M @ xm_w1 + xb1); gate dot ----
    zero_c(c);
    warp_gemm(sb + SMM_OFF + (uint32_t)((m0 + gid) * LD2 + tig * 2) * 2,
              sb + SW2B_OFF + (uint32_t)((n0 + gid) * LD2 + tig * 2) * 2,
              LD2 * 2, 8, c);
    {
        float p[2][2] = {{0.f, 0.f}, {0.f, 0.f}};
#pragma unroll
        for (int mt = 0; mt < 2; mt++)
#pragma unroll
            for (int nt = 0; nt < 8; nt++) {
                int col = n0 + nt * 8 + tig * 2;
                float* cc = c[mt][nt];
                p[mt][0] += siluf(cc[0] + sXB1[col]) * sXW2[col]
                          + siluf(cc[1] + sXB1[col + 1]) * sXW2[col + 1];
                p[mt][1] += siluf(cc[2] + sXB1[col]) * sXW2[col]
                          + siluf(cc[3] + sXB1[col + 1]) * sXW2[col + 1];
            }
#pragma unroll
        for (int mt = 0; mt < 2; mt++)
#pragma unroll
            for (int hh = 0; hh < 2; hh++) {
                float v = p[mt][hh];
                v += __shfl_xor_sync(0xffffffffu, v, 1);
                v += __shfl_xor_sync(0xffffffffu, v, 2);
                if (tig == 0)
                    sPart[(wid & 1) * 128 + m0 + mt * 16 + hh * 8 + gid] = v;
            }
    }
    __syncthreads();

    if (tid < 128) {
        float g = tanhf(sPart[tid] + sPart[128 + tid]);
        float coef = g / (sqrtf(sDsq[tid] + 1e-8f) + 1.f);
        int d = sDst[tid];
        float v0 = sRlX[tid] * coef, v1 = sRlY[tid] * coef, v2 = sRlZ[tid] * coef;
        atomicAdd(&x_out[d * 3 + 0], v0);
        atomicAdd(&x_out[d * 3 + 1], v1);
        atomicAdd(&x_out[d * 3 + 2], v2);
    }
}

// ---------------------------------------------------------------------------
// Node kernel: h_out = h + node_mlp(concat(mi, h))
// ---------------------------------------------------------------------------
__global__ void __launch_bounds__(NT, 1) egnn_node_kernel(
    const float* __restrict__ h,
    const float* __restrict__ nm_b1, const float* __restrict__ nm_b2,
    float* __restrict__ h_out)
{
    extern __shared__ unsigned char sm[];
    const uint32_t sb = smem_u32(sm);
    const int tid  = threadIdx.x;
    const int wid  = tid >> 5;
    const int lane = tid & 31;
    const int gid  = lane >> 2;
    const int tig  = lane & 3;
    const int m0   = (wid >> 1) * 32;
    const int n0   = (wid & 1) * 64;
    const int nb   = blockIdx.x * ME;

    float* sB1 = (float*)(sm + OFF_B1);
    float* sB2 = (float*)(sm + OFF_B2);

    if (tid < 128) { sB1[tid] = nm_b1[tid]; sB2[tid] = nm_b2[tid]; }

    // gather [mi | h] rows (bf16)
    for (int q = tid; q < ME * 32; q += NT) {
        int e = q >> 5, ch = q & 31;
        int n = nb + e;
        int col = (ch & 15) * 8 + ((ch < 16) ? 0 : 128);
        uint4 w = make_uint4(0, 0, 0, 0);
        if (n < NN) {
            const float* src = (ch < 16) ? (g_mi + (size_t)n * HIDD)
                                         : (h    + (size_t)n * HIDD);
            const float4* sp = (const float4*)(src + (ch & 15) * 8);
            float4 v0 = sp[0], v1 = sp[1];
            w.x = pk(v0.x, v0.y); w.y = pk(v0.z, v0.w);
            w.z = pk(v1.x, v1.y); w.w = pk(v1.z, v1.w);
        }
        sts128(sb + NA_OFF + (uint32_t)(e * LD3 + col) * 2, w);
    }
    {
        uint4* d = (uint4*)(sm + NW_OFF);
        const uint4* s = (const uint4*)g_nw1t;
        for (int q = tid; q < 128 * LD3 * 2 / 16; q += NT) d[q] = s[q];
    }
    __syncthreads();

    float c[2][8][4];

    // GEMM1: silu(A @ nm_w1 + b1) -> S
    zero_c(c);
    warp_gemm(sb + NA_OFF + (uint32_t)((m0 + gid) * LD3 + tig * 2) * 2,
              sb + NW_OFF + (uint32_t)((n0 + gid) * LD3 + tig * 2) * 2,
              LD3 * 2, K3 / 16, c);
    __syncthreads();

#pragma unroll
    for (int mt = 0; mt < 2; mt++)
#pragma unroll
        for (int nt = 0; nt < 8; nt++) {
            int row = m0 + mt * 16 + gid;
            int col = n0 + nt * 8 + tig * 2;
            float* cc = c[mt][nt];
            sts32(sb + NA_OFF + (uint32_t)(row * LD2 + col) * 2,
                  pk(siluf(cc[0] + sB1[col]), siluf(cc[1] + sB1[col + 1])));
            sts32(sb + NA_OFF + (uint32_t)((row + 8) * LD2 + col) * 2,
                  pk(siluf(cc[2] + sB1[col]), siluf(cc[3] + sB1[col + 1])));
        }
    {
        uint4* d = (uint4*)(sm + NW_OFF);
        const uint4* s = (const uint4*)g_nw2t;
        for (int q = tid; q < 128 * LD2 * 2 / 16; q += NT) d[q] = s[q];
    }
    __syncthreads();

    // GEMM2 + residual epilogue
    zero_c(c);
    warp_gemm(sb + NA_OFF + (uint32_t)((m0 + gid) * LD2 + tig * 2) * 2,
              sb + NW_OFF + (uint32_t)((n0 + gid) * LD2 + tig * 2) * 2,
              LD2 * 2, 8, c);

#pragma unroll
    for (int mt = 0; mt < 2; mt++)
#pragma unroll
        for (int nt = 0; nt < 8; nt++) {
            int row = m0 + mt * 16 + gid;
            int col = n0 + nt * 8 + tig * 2;
            float* cc = c[mt][nt];
            int na = nb + row, nb2 = nb + row + 8;
            if (na < NN) {
                const float2 hv = *(const float2*)(h + (size_t)na * HIDD + col);
                float2 o = make_float2(cc[0] + sB2[col] + hv.x,
                                       cc[1] + sB2[col + 1] + hv.y);
                *(float2*)(h_out + (size_t)na * HIDD + col) = o;
            }
            if (nb2 < NN) {
                const float2 hv = *(const float2*)(h + (size_t)nb2 * HIDD + col);
                float2 o = make_float2(cc[2] + sB2[col] + hv.x,
                                       cc[3] + sB2[col + 1] + hv.y);
                *(float2*)(h_out + (size_t)nb2 * HIDD + col) = o;
            }
        }
}

// ---------------------------------------------------------------------------
extern "C" void kernel_launch(void* const* d_in, const int* in_sizes, int n_in,
                              void* d_out, int out_size) {
    const float* h     = (const float*)d_in[0];
    const float* x     = (const float*)d_in[1];
    const int*   eidx  = (const int*)  d_in[2];
    const float* eattr = (const float*)d_in[3];
    const float* em_w1 = (const float*)d_in[4];
    const float* em_b1 = (const float*)d_in[5];
    const float* em_w2 = (const float*)d_in[6];
    const float* em_b2 = (const float*)d_in[7];
    const float* ei_w  = (const float*)d_in[8];
    const float* ei_b  = (const float*)d_in[9];
    const float* xm_w1 = (const float*)d_in[10];
    const float* xm_b1 = (const float*)d_in[11];
    const float* xm_w2 = (const float*)d_in[12];
    const float* nm_w1 = (const float*)d_in[13];
    const float* nm_b1 = (const float*)d_in[14];
    const float* nm_w2 = (const float*)d_in[15];
    const float* nm_b2 = (const float*)d_in[16];

    float* out   = (float*)d_out;
    float* h_out = out;                        // [NN, 128]
    float* x_out = out + (size_t)NN * HIDD;    // [NN, 3]

    cudaFuncSetAttribute(egnn_edge_kernel,
                         cudaFuncAttributeMaxDynamicSharedMemorySize, EDGE_SMEM);
    cudaFuncSetAttribute(egnn_node_kernel,
                         cudaFuncAttributeMaxDynamicSharedMemorySize, NODE_SMEM);

    egnn_init_kernel<<<1024, 256>>>(x, x_out);
    egnn_prep_kernel<<<128, 256>>>(em_w1, em_w2, xm_w1, nm_w1, nm_w2);
    egnn_edge_kernel<<<NE / ME, NT, EDGE_SMEM>>>(
        h, x, eidx, eattr, em_b1, em_b2, ei_w, ei_b, xm_b1, xm_w2, x_out);
    egnn_node_kernel<<<(NN + ME - 1) / ME, NT, NODE_SMEM>>>(
        h, nm_b1, nm_b2, h_out);
}

// round 6
// speedup vs baseline: 5.6422x; 1.7291x over previous
#include <cuda_runtime.h>
#include <cuda_bf16.h>
#include <cstdint>

#define NN   50000
#define NE   640000
#define HIDD 128
#define EF   16
#define DIN  273
#define K1   288          // GEMM1 K padded
#define LD1  296          // elems; 592 B row stride (K=288 tiles)
#define LD2  136          // 272 B (K=128 tiles)
#define K3   256
#define LD3  264          // 528 B (K=256 tiles)
#define ME   128          // rows per CTA
#define NT   512          // 16 warps

// ---- misc smem offsets (bytes) ----
#define OFF_B1   0
#define OFF_B2   512
#define OFF_EIW  1024
#define OFF_XB1  1536
#define OFF_XW2  2048
#define OFF_DSQ  2560
#define OFF_EIJ  3072
#define OFF_RLX  3584
#define OFF_RLY  4096
#define OFF_RLZ  4608
#define OFF_DST  5120
#define OFF_SRC  5632
#define OFF_PART 6144      // fp32[512]
#define SA_OFF   8192                        // A1 [128][LD1] bf16 (75776 B)
#define SS_OFF   8192                        // S  [128][LD2] (reuse of A1)
#define SMM_OFF  (8192 + 34816)              // M  [128][LD2]
#define SW_OFF   (8192 + 128 * LD1 * 2)      // 83968: W1t; later W2t
#define SW2B_OFF (SW_OFF + 34816)            // XW1t
#define EDGE_SMEM (SW_OFF + 128 * LD1 * 2)   // 159744

#define NA_OFF   8192                        // [128][LD3]; S reuse
#define NW_OFF   (8192 + 128 * LD3 * 2)      // nw1t; nw2t reuse
#define NODE_SMEM (NW_OFF + 128 * LD3 * 2)   // 143360

__device__ float g_mi[(size_t)NN * HIDD];
__device__ __align__(16) __nv_bfloat16 g_w1t [128 * LD1];
__device__ __align__(16) __nv_bfloat16 g_w2t [128 * LD2];
__device__ __align__(16) __nv_bfloat16 g_xw1t[128 * LD2];
__device__ __align__(16) __nv_bfloat16 g_nw1t[128 * LD3];
__device__ __align__(16) __nv_bfloat16 g_nw2t[128 * LD2];

// ---------------------------------------------------------------------------
__device__ __forceinline__ uint32_t smem_u32(const void* p) {
    uint32_t a;
    asm("{ .reg .u64 t; cvta.to.shared.u64 t, %1; cvt.u32.u64 %0, t; }"
        : "=r"(a) : "l"(p));
    return a;
}
__device__ __forceinline__ void sts32(uint32_t a, uint32_t v) {
    asm volatile("st.shared.b32 [%0], %1;" :: "r"(a), "r"(v));
}
__device__ __forceinline__ void sts128(uint32_t a, uint4 v) {
    asm volatile("st.shared.v4.b32 [%0], {%1,%2,%3,%4};"
                 :: "r"(a), "r"(v.x), "r"(v.y), "r"(v.z), "r"(v.w));
}
__device__ __forceinline__ void cpa16(uint32_t saddr, const void* g) {
    asm volatile("cp.async.cg.shared.global [%0], [%1], 16;"
                 :: "r"(saddr), "l"(g));
}
#define CPA_COMMIT() asm volatile("cp.async.commit_group;")
#define CPA_WAIT0()  asm volatile("cp.async.wait_group 0;" ::: "memory")

__device__ __forceinline__ uint32_t pk(float lo, float hi) {
    uint32_t l = __bfloat16_as_ushort(__float2bfloat16(lo));
    uint32_t h = __bfloat16_as_ushort(__float2bfloat16(hi));
    return l | (h << 16);
}
__device__ __forceinline__ float ubf_lo(uint32_t v) {
    return __bfloat162float(__ushort_as_bfloat16((unsigned short)(v & 0xFFFF)));
}
__device__ __forceinline__ float ubf_hi(uint32_t v) {
    return __bfloat162float(__ushort_as_bfloat16((unsigned short)(v >> 16)));
}
__device__ __forceinline__ float siluf(float v) { return v / (1.f + __expf(-v)); }

__device__ __forceinline__ void mma_bf16(float* c,
                                         uint32_t a0, uint32_t a1, uint32_t a2, uint32_t a3,
                                         uint32_t b0, uint32_t b1) {
    asm volatile("mma.sync.aligned.m16n8k16.row.col.f32.bf16.bf16.f32 "
                 "{%0,%1,%2,%3}, {%4,%5,%6,%7}, {%8,%9}, {%0,%1,%2,%3};"
                 : "+f"(c[0]), "+f"(c[1]), "+f"(c[2]), "+f"(c[3])
                 : "r"(a0), "r"(a1), "r"(a2), "r"(a3), "r"(b0), "r"(b1));
}
__device__ __forceinline__ void ldsm4(uint32_t a, uint32_t& r0, uint32_t& r1,
                                      uint32_t& r2, uint32_t& r3) {
    asm volatile("ldmatrix.sync.aligned.m8n8.x4.shared.b16 {%0,%1,%2,%3}, [%4];"
                 : "=r"(r0), "=r"(r1), "=r"(r2), "=r"(r3) : "r"(a));
}

// warp tile 32(m) x 32(n); A rows m, B rows n, both row-major over k, stride ld bytes.
// aAddr: lane addr = Abase + (m0 + (lane&15))*ld + ((lane>>4)<<4)
// bAddr: lane addr = Bbase + (n0 + (lane&7) + ((lane>>4)<<3))*ld + (((lane>>3)&1)<<4)
__device__ __forceinline__ void warp_gemm32(uint32_t aAddr, uint32_t bAddr,
                                            uint32_t ld, int ksteps, float c[2][4][4]) {
    const uint32_t mstep = 16u * ld;
#pragma unroll 2
    for (int ks = 0; ks < ksteps; ks++) {
        uint32_t A[2][4], B[2][4];
        ldsm4(aAddr,         A[0][0], A[0][1], A[0][2], A[0][3]);
        ldsm4(aAddr + mstep, A[1][0], A[1][1], A[1][2], A[1][3]);
        ldsm4(bAddr,         B[0][0], B[0][1], B[0][2], B[0][3]);
        ldsm4(bAddr + mstep, B[1][0], B[1][1], B[1][2], B[1][3]);
        aAddr += 32; bAddr += 32;
#pragma unroll
        for (int mt = 0; mt < 2; mt++)
#pragma unroll
            for (int nt = 0; nt < 4; nt++)
                mma_bf16(c[mt][nt],
                         A[mt][0], A[mt][1], A[mt][2], A[mt][3],
                         B[nt >> 1][(nt & 1) * 2], B[nt >> 1][(nt & 1) * 2 + 1]);
    }
}
__device__ __forceinline__ void zero_c(float c[2][4][4]) {
#pragma unroll
    for (int i = 0; i < 2; i++)
#pragma unroll
        for (int j = 0; j < 4; j++)
#pragma unroll
            for (int k = 0; k < 4; k++) c[i][j][k] = 0.f;
}

// ---------------------------------------------------------------------------
__global__ void egnn_init_kernel(const float* __restrict__ x, float* __restrict__ x_out) {
    int i = blockIdx.x * blockDim.x + threadIdx.x;
    int s = gridDim.x * blockDim.x;
    for (int j = i; j < NN * HIDD; j += s) g_mi[j] = 0.f;
    for (int j = i; j < NN * 3;   j += s) x_out[j] = x[j];
}

__global__ void egnn_prep_kernel(const float* __restrict__ em_w1, const float* __restrict__ em_w2,
                                 const float* __restrict__ xm_w1, const float* __restrict__ nm_w1,
                                 const float* __restrict__ nm_w2) {
    const int T1 = 128 * LD1;
    const int T2 = T1 + 128 * LD2;
    const int T3 = T2 + 128 * LD2;
    const int T4 = T3 + 128 * LD3;
    const int T5 = T4 + 128 * LD2;
    int i = blockIdx.x * blockDim.x + threadIdx.x;
    int s = gridDim.x * blockDim.x;
    for (int p = i; p < T5; p += s) {
        const float* W; __nv_bfloat16* dst; int kv, ld, pl = p;
        if (p < T1)      { W = em_w1; dst = g_w1t;  kv = DIN; ld = LD1; }
        else if (p < T2) { W = em_w2; dst = g_w2t;  kv = 128; ld = LD2; pl = p - T1; }
        else if (p < T3) { W = xm_w1; dst = g_xw1t; kv = 128; ld = LD2; pl = p - T2; }
        else if (p < T4) { W = nm_w1; dst = g_nw1t; kv = 256; ld = LD3; pl = p - T3; }
        else             { W = nm_w2; dst = g_nw2t; kv = 128; ld = LD2; pl = p - T4; }
        int n = pl / ld, k = pl % ld;
        float v = (k < kv) ? W[(size_t)k * 128 + n] : 0.f;
        dst[pl] = __float2bfloat16(v);
    }
}

// ---------------------------------------------------------------------------
// Edge kernel: 128 edges per CTA, 16 warps, ldmatrix + HMMA.
// ---------------------------------------------------------------------------
__global__ void __launch_bounds__(NT, 1) egnn_edge_kernel(
    const float* __restrict__ h,     const float* __restrict__ x,
    const int*   __restrict__ eidx,  const float* __restrict__ eattr,
    const float* __restrict__ em_b1, const float* __restrict__ em_b2,
    const float* __restrict__ ei_w,  const float* __restrict__ ei_b,
    const float* __restrict__ xm_b1, const float* __restrict__ xm_w2,
    float* __restrict__ x_out)
{
    extern __shared__ unsigned char sm[];
    const uint32_t sb = smem_u32(sm);
    const int tid  = threadIdx.x;
    const int wid  = tid >> 5;
    const int lane = tid & 31;
    const int gid  = lane >> 2;
    const int tig  = lane & 3;
    const int m0   = (wid >> 2) * 32;
    const int n0   = (wid & 3) * 32;
    const int e0   = blockIdx.x * ME;

    float* sB1  = (float*)(sm + OFF_B1);
    float* sB2  = (float*)(sm + OFF_B2);
    float* sEIW = (float*)(sm + OFF_EIW);
    float* sXB1 = (float*)(sm + OFF_XB1);
    float* sXW2 = (float*)(sm + OFF_XW2);
    float* sDsq = (float*)(sm + OFF_DSQ);
    float* sEij = (float*)(sm + OFF_EIJ);
    float* sRlX = (float*)(sm + OFF_RLX);
    float* sRlY = (float*)(sm + OFF_RLY);
    float* sRlZ = (float*)(sm + OFF_RLZ);
    int*   sDst = (int*)  (sm + OFF_DST);
    int*   sSrc = (int*)  (sm + OFF_SRC);
    float* sPart= (float*)(sm + OFF_PART);

    // kick off W1t copy (async) — overlaps with gather below
    for (int q = tid; q < 128 * LD1 * 2 / 16; q += NT)
        cpa16(sb + SW_OFF + q * 16, (const unsigned char*)g_w1t + q * 16);
    CPA_COMMIT();

    if (tid < 128) {
        sB1[tid]  = em_b1[tid]; sB2[tid] = em_b2[tid]; sEIW[tid] = ei_w[tid];
        sXB1[tid] = xm_b1[tid]; sXW2[tid] = xm_w2[tid];
        int e  = e0 + tid;
        int s_ = eidx[e], d_ = eidx[NE + e];
        sSrc[tid] = s_; sDst[tid] = d_;
        float rx = x[d_ * 3 + 0] - x[s_ * 3 + 0];
        float ry = x[d_ * 3 + 1] - x[s_ * 3 + 1];
        float rz = x[d_ * 3 + 2] - x[s_ * 3 + 2];
        sRlX[tid] = rx; sRlY[tid] = ry; sRlZ[tid] = rz;
        sDsq[tid] = rx * rx + ry * ry + rz * rz;
    }
    __syncthreads();

    // gather A1 rows (bf16): [h[dst] | h[src] | dsq | eattr | 0]
    for (int q = tid; q < ME * 36; q += NT) {
        int e = q / 36, ch = q % 36;
        uint4 w;
        int col;
        if (ch < 32) {
            int node = (ch < 16) ? sDst[e] : sSrc[e];
            col = (ch & 15) * 8 + ((ch < 16) ? 0 : 128);
            const float4* hp = (const float4*)(h + (size_t)node * HIDD + (ch & 15) * 8);
            float4 v0 = hp[0], v1 = hp[1];
            w.x = pk(v0.x, v0.y); w.y = pk(v0.z, v0.w);
            w.z = pk(v1.x, v1.y); w.w = pk(v1.z, v1.w);
        } else {
            col = 256 + (ch - 32) * 8;
            float v[8];
#pragma unroll
            for (int j = 0; j < 8; j++) {
                int idx = col + j - 256;
                float f = 0.f;
                if (idx == 0) f = sDsq[e];
                else if (idx <= EF) f = eattr[(size_t)(e0 + e) * EF + (idx - 1)];
                v[j] = f;
            }
            w.x = pk(v[0], v[1]); w.y = pk(v[2], v[3]);
            w.z = pk(v[4], v[5]); w.w = pk(v[6], v[7]);
        }
        sts128(sb + SA_OFF + (uint32_t)(e * LD1 + col) * 2, w);
    }
    CPA_WAIT0();
    __syncthreads();

    float c[2][4][4];
    const uint32_t aOffA = (uint32_t)(m0 + (lane & 15)) * (LD1 * 2) + ((lane >> 4) << 4);
    const uint32_t bOffA = (uint32_t)(n0 + (lane & 7) + ((lane >> 4) << 3)) * (LD1 * 2)
                         + (((lane >> 3) & 1) << 4);
    const uint32_t aOff2 = (uint32_t)(m0 + (lane & 15)) * (LD2 * 2) + ((lane >> 4) << 4);
    const uint32_t bOff2 = (uint32_t)(n0 + (lane & 7) + ((lane >> 4) << 3)) * (LD2 * 2)
                         + (((lane >> 3) & 1) << 4);

    // ---- GEMM1: silu(A1 @ W1 + b1) -> S ----
    zero_c(c);
    warp_gemm32(sb + SA_OFF + aOffA, sb + SW_OFF + bOffA, LD1 * 2, K1 / 16, c);
    __syncthreads();   // all warps done reading A1 / W1t

    // async: W2t over W1t region, XW1t
    for (int q = tid; q < 128 * LD2 * 2 / 16; q += NT) {
        cpa16(sb + SW_OFF  + q * 16, (const unsigned char*)g_w2t  + q * 16);
        cpa16(sb + SW2B_OFF + q * 16, (const unsigned char*)g_xw1t + q * 16);
    }
    CPA_COMMIT();

#pragma unroll
    for (int mt = 0; mt < 2; mt++)
#pragma unroll
        for (int nt = 0; nt < 4; nt++) {
            int row = m0 + mt * 16 + gid;
            int col = n0 + nt * 8 + tig * 2;
            float* cc = c[mt][nt];
            sts32(sb + SS_OFF + (uint32_t)(row * LD2 + col) * 2,
                  pk(siluf(cc[0] + sB1[col]), siluf(cc[1] + sB1[col + 1])));
            sts32(sb + SS_OFF + (uint32_t)((row + 8) * LD2 + col) * 2,
                  pk(siluf(cc[2] + sB1[col]), siluf(cc[3] + sB1[col + 1])));
        }
    CPA_WAIT0();
    __syncthreads();

    // ---- GEMM2: mij = S @ W2 + b2 -> M ; eij partial dot ----
    zero_c(c);
    warp_gemm32(sb + SS_OFF + aOff2, sb + SW_OFF + bOff2, LD2 * 2, 8, c);
    {
        float p[2][2] = {{0.f, 0.f}, {0.f, 0.f}};
#pragma unroll
        for (int mt = 0; mt < 2; mt++)
#pragma unroll
            for (int nt = 0; nt < 4; nt++) {
                int row = m0 + mt * 16 + gid;
                int col = n0 + nt * 8 + tig * 2;
                float* cc = c[mt][nt];
                float v0 = cc[0] + sB2[col], v1 = cc[1] + sB2[col + 1];
                float v2 = cc[2] + sB2[col], v3 = cc[3] + sB2[col + 1];
                sts32(sb + SMM_OFF + (uint32_t)(row * LD2 + col) * 2, pk(v0, v1));
                sts32(sb + SMM_OFF + (uint32_t)((row + 8) * LD2 + col) * 2, pk(v2, v3));
                p[mt][0] += v0 * sEIW[col] + v1 * sEIW[col + 1];
                p[mt][1] += v2 * sEIW[col] + v3 * sEIW[col + 1];
            }
#pragma unroll
        for (int mt = 0; mt < 2; mt++)
#pragma unroll
            for (int hh = 0; hh < 2; hh++) {
                float v = p[mt][hh];
                v += __shfl_xor_sync(0xffffffffu, v, 1);
                v += __shfl_xor_sync(0xffffffffu, v, 2);
                if (tig == 0)
                    sPart[(wid & 3) * 128 + m0 + mt * 16 + hh * 8 + gid] = v;
            }
    }
    __syncthreads();

    if (tid < 128) {
        float t = sPart[tid] + sPart[128 + tid] + sPart[256 + tid] + sPart[384 + tid]
                + ei_b[0];
        sEij[tid] = 1.f / (1.f + __expf(-t));
    }
    __syncthreads();

    // ---- scatter: g_mi[dst] += mij * eij  (v4 reductions, fp32) ----
    for (int q = tid; q < ME * 32; q += NT) {
        int e = q >> 5, c4 = (q & 31) * 4;
        const uint32_t* mp = (const uint32_t*)(sm + SMM_OFF + (uint32_t)(e * LD2 + c4) * 2);
        uint32_t u0 = mp[0], u1 = mp[1];
        float ei = sEij[e];
        float v0 = ubf_lo(u0) * ei, v1 = ubf_hi(u0) * ei;
        float v2 = ubf_lo(u1) * ei, v3 = ubf_hi(u1) * ei;
        float* g = g_mi + (size_t)sDst[e] * HIDD + c4;
        asm volatile("red.global.add.v4.f32 [%0], {%1,%2,%3,%4};"
                     :: "l"(g), "f"(v0), "f"(v1), "f"(v2), "f"(v3) : "memory");
    }

    // ---- GEMM3: u = silu(M @ xm_w1 + xb1); gate dot ----
    zero_c(c);
    warp_gemm32(sb + SMM_OFF + aOff2, sb + SW2B_OFF + bOff2, LD2 * 2, 8, c);
    {
        float p[2][2] = {{0.f, 0.f}, {0.f, 0.f}};
#pragma unroll
        for (int mt = 0; mt < 2; mt++)
#pragma unroll
            for (int nt = 0; nt < 4; nt++) {
                int col = n0 + nt * 8 + tig * 2;
                float* cc = c[mt][nt];
                p[mt][0] += siluf(cc[0] + sXB1[col]) * sXW2[col]
                          + siluf(cc[1] + sXB1[col + 1]) * sXW2[col + 1];
                p[mt][1] += siluf(cc[2] + sXB1[col]) * sXW2[col]
                          + siluf(cc[3] + sXB1[col + 1]) * sXW2[col + 1];
            }
#pragma unroll
        for (int mt = 0; mt < 2; mt++)
#pragma unroll
            for (int hh = 0; hh < 2; hh++) {
                float v = p[mt][hh];
                v += __shfl_xor_sync(0xffffffffu, v, 1);
                v += __shfl_xor_sync(0xffffffffu, v, 2);
                if (tig == 0)
                    sPart[(wid & 3) * 128 + m0 + mt * 16 + hh * 8 + gid] = v;
            }
    }
    __syncthreads();

    if (tid < 128) {
        float g = tanhf(sPart[tid] + sPart[128 + tid] + sPart[256 + tid] + sPart[384 + tid]);
        float coef = g / (sqrtf(sDsq[tid] + 1e-8f) + 1.f);
        int d = sDst[tid];
        atomicAdd(&x_out[d * 3 + 0], sRlX[tid] * coef);
        atomicAdd(&x_out[d * 3 + 1], sRlY[tid] * coef);
        atomicAdd(&x_out[d * 3 + 2], sRlZ[tid] * coef);
    }
}

// ---------------------------------------------------------------------------
// Node kernel: h_out = h + node_mlp(concat(mi, h))
// ---------------------------------------------------------------------------
__global__ void __launch_bounds__(NT, 1) egnn_node_kernel(
    const float* __restrict__ h,
    const float* __restrict__ nm_b1, const float* __restrict__ nm_b2,
    float* __restrict__ h_out)
{
    extern __shared__ unsigned char sm[];
    const uint32_t sb = smem_u32(sm);
    const int tid  = threadIdx.x;
    const int wid  = tid >> 5;
    const int lane = tid & 31;
    const int gid  = lane >> 2;
    const int tig  = lane & 3;
    const int m0   = (wid >> 2) * 32;
    const int n0   = (wid & 3) * 32;
    const int nb   = blockIdx.x * ME;

    float* sB1 = (float*)(sm + OFF_B1);
    float* sB2 = (float*)(sm + OFF_B2);

    for (int q = tid; q < 128 * LD3 * 2 / 16; q += NT)
        cpa16(sb + NW_OFF + q * 16, (const unsigned char*)g_nw1t + q * 16);
    CPA_COMMIT();

    if (tid < 128) { sB1[tid] = nm_b1[tid]; sB2[tid] = nm_b2[tid]; }

    // gather [mi | h] rows (bf16)
    for (int q = tid; q < ME * 32; q += NT) {
        int e = q >> 5, ch = q & 31;
        int n = nb + e;
        int col = (ch & 15) * 8 + ((ch < 16) ? 0 : 128);
        uint4 w = make_uint4(0, 0, 0, 0);
        if (n < NN) {
            const float* src = (ch < 16) ? (g_mi + (size_t)n * HIDD)
                                         : (h    + (size_t)n * HIDD);
            const float4* sp = (const float4*)(src + (ch & 15) * 8);
            float4 v0 = sp[0], v1 = sp[1];
            w.x = pk(v0.x, v0.y); w.y = pk(v0.z, v0.w);
            w.z = pk(v1.x, v1.y); w.w = pk(v1.z, v1.w);
        }
        sts128(sb + NA_OFF + (uint32_t)(e * LD3 + col) * 2, w);
    }
    CPA_WAIT0();
    __syncthreads();

    float c[2][4][4];
    const uint32_t aOff3 = (uint32_t)(m0 + (lane & 15)) * (LD3 * 2) + ((lane >> 4) << 4);
    const uint32_t bOff3 = (uint32_t)(n0 + (lane & 7) + ((lane >> 4) << 3)) * (LD3 * 2)
                         + (((lane >> 3) & 1) << 4);
    const uint32_t aOff2 = (uint32_t)(m0 + (lane & 15)) * (LD2 * 2) + ((lane >> 4) << 4);
    const uint32_t bOff2 = (uint32_t)(n0 + (lane & 7) + ((lane >> 4) << 3)) * (LD2 * 2)
                         + (((lane >> 3) & 1) << 4);

    // GEMM1: silu(A @ nm_w1 + b1) -> S
    zero_c(c);
    warp_gemm32(sb + NA_OFF + aOff3, sb + NW_OFF + bOff3, LD3 * 2, K3 / 16, c);
    __syncthreads();

    for (int q = tid; q < 128 * LD2 * 2 / 16; q += NT)
        cpa16(sb + NW_OFF + q * 16, (const unsigned char*)g_nw2t + q * 16);
    CPA_COMMIT();

#pragma unroll
    for (int mt = 0; mt < 2; mt++)
#pragma unroll
        for (int nt = 0; nt < 4; nt++) {
            int row = m0 + mt * 16 + gid;
            int col = n0 + nt * 8 + tig * 2;
            float* cc = c[mt][nt];
            sts32(sb + NA_OFF + (uint32_t)(row * LD2 + col) * 2,
                  pk(siluf(cc[0] + sB1[col]), siluf(cc[1] + sB1[col + 1])));
            sts32(sb + NA_OFF + (uint32_t)((row + 8) * LD2 + col) * 2,
                  pk(siluf(cc[2] + sB1[col]), siluf(cc[3] + sB1[col + 1])));
        }
    CPA_WAIT0();
    __syncthreads();

    // GEMM2 + residual epilogue
    zero_c(c);
    warp_gemm32(sb + NA_OFF + aOff2, sb + NW_OFF + bOff2, LD2 * 2, 8, c);

#pragma unroll
    for (int mt = 0; mt < 2; mt++)
#pragma unroll
        for (int nt = 0; nt < 4; nt++) {
            int row = m0 + mt * 16 + gid;
            int col = n0 + nt * 8 + tig * 2;
            float* cc = c[mt][nt];
            int na = nb + row, na2 = nb + row + 8;
            if (na < NN) {
                const float2 hv = *(const float2*)(h + (size_t)na * HIDD + col);
                *(float2*)(h_out + (size_t)na * HIDD + col) =
                    make_float2(cc[0] + sB2[col] + hv.x, cc[1] + sB2[col + 1] + hv.y);
            }
            if (na2 < NN) {
                const float2 hv = *(const float2*)(h + (size_t)na2 * HIDD + col);
                *(float2*)(h_out + (size_t)na2 * HIDD + col) =
                    make_float2(cc[2] + sB2[col] + hv.x, cc[3] + sB2[col + 1] + hv.y);
            }
        }
}

// ---------------------------------------------------------------------------
extern "C" void kernel_launch(void* const* d_in, const int* in_sizes, int n_in,
                              void* d_out, int out_size) {
    const float* h     = (const float*)d_in[0];
    const float* x     = (const float*)d_in[1];
    const int*   eidx  = (const int*)  d_in[2];
    const float* eattr = (const float*)d_in[3];
    const float* em_w1 = (const float*)d_in[4];
    const float* em_b1 = (const float*)d_in[5];
    const float* em_w2 = (const float*)d_in[6];
    const float* em_b2 = (const float*)d_in[7];
    const float* ei_w  = (const float*)d_in[8];
    const float* ei_b  = (const float*)d_in[9];
    const float* xm_w1 = (const float*)d_in[10];
    const float* xm_b1 = (const float*)d_in[11];
    const float* xm_w2 = (const float*)d_in[12];
    const float* nm_w1 = (const float*)d_in[13];
    const float* nm_b1 = (const float*)d_in[14];
    const float* nm_w2 = (const float*)d_in[15];
    const float* nm_b2 = (const float*)d_in[16];

    float* out   = (float*)d_out;
    float* h_out = out;                        // [NN, 128]
    float* x_out = out + (size_t)NN * HIDD;    // [NN, 3]

    cudaFuncSetAttribute(egnn_edge_kernel,
                         cudaFuncAttributeMaxDynamicSharedMemorySize, EDGE_SMEM);
    cudaFuncSetAttribute(egnn_node_kernel,
                         cudaFuncAttributeMaxDynamicSharedMemorySize, NODE_SMEM);

    egnn_init_kernel<<<1024, 256>>>(x, x_out);
    egnn_prep_kernel<<<128, 256>>>(em_w1, em_w2, xm_w1, nm_w1, nm_w2);
    egnn_edge_kernel<<<NE / ME, NT, EDGE_SMEM>>>(
        h, x, eidx, eattr, em_b1, em_b2, ei_w, ei_b, xm_b1, xm_w2, x_out);
    egnn_node_kernel<<<(NN + ME - 1) / ME, NT, NODE_SMEM>>>(
        h, nm_b1, nm_b2, h_out);
}

// round 7
// speedup vs baseline: 10.0869x; 1.7878x over previous
#include <cuda_runtime.h>
#include <cuda_bf16.h>
#include <cstdint>

#define NN   50000
#define NE   640000
#define HIDD 128
#define EF   16
#define LD2  136          // elems; 272 B row stride (K=128 tiles)
#define LDF  40           // feat tiles: 80 B row stride (K=32)
#define ME   128          // rows per CTA
#define NT   512          // 16 warps

#define WTILE (128 * LD2)             // 17408 elems / 34816 B
#define WBYTES 34816
#define FBYTES (128 * LDF * 2)        // 10240

// ---- edge kernel smem (bytes) ----
#define OFF_B1   0
#define OFF_B2   512
#define OFF_EIW  1024
#define OFF_XB1  1536
#define OFF_XW2  2048
#define OFF_DSQ  2560
#define OFF_EIJ  3072
#define OFF_RLX  3584
#define OFF_RLY  4096
#define OFF_RLZ  4608
#define OFF_DST  5120
#define OFF_SRC  5632
#define OFF_PART 6144                 // fp32[512] -> ends 8192
#define R1_OFF   8192                 // Psum, later M   [128][LD2] bf16
#define R2_OFF   (R1_OFF + WBYTES)    // S
#define R3_OFF   (R2_OFF + WBYTES)    // featA+W1c, later W2t, later XW1t
#define FA_OFF   R3_OFF
#define FW_OFF   (R3_OFF + FBYTES)
#define EDGE_SMEM (R3_OFF + WBYTES)   // 112640

// ---- node / pre kernels ----
#define NA_OFF   1024
#define NW_OFF   (NA_OFF + WBYTES)
#define NODE_SMEM (NW_OFF + WBYTES)   // 70656

__device__ float g_mi[(size_t)NN * HIDD];
__device__ float g_pa[(size_t)NN * HIDD];
__device__ float g_pb[(size_t)NN * HIDD];
__device__ float g_ph[(size_t)NN * HIDD];
__device__ __align__(16) __nv_bfloat16 g_w1at [WTILE];
__device__ __align__(16) __nv_bfloat16 g_w1bt [WTILE];
__device__ __align__(16) __nv_bfloat16 g_w1ct [128 * LDF];
__device__ __align__(16) __nv_bfloat16 g_w2t  [WTILE];
__device__ __align__(16) __nv_bfloat16 g_xw1t [WTILE];
__device__ __align__(16) __nv_bfloat16 g_nw1at[WTILE];
__device__ __align__(16) __nv_bfloat16 g_nw1bt[WTILE];
__device__ __align__(16) __nv_bfloat16 g_nw2t [WTILE];

// ---------------------------------------------------------------------------
__device__ __forceinline__ uint32_t smem_u32(const void* p) {
    uint32_t a;
    asm("{ .reg .u64 t; cvta.to.shared.u64 t, %1; cvt.u32.u64 %0, t; }"
        : "=r"(a) : "l"(p));
    return a;
}
__device__ __forceinline__ uint32_t lds32(uint32_t a) {
    uint32_t v;
    asm volatile("ld.shared.b32 %0, [%1];" : "=r"(v) : "r"(a));
    return v;
}
__device__ __forceinline__ void sts32(uint32_t a, uint32_t v) {
    asm volatile("st.shared.b32 [%0], %1;" :: "r"(a), "r"(v));
}
__device__ __forceinline__ void sts128(uint32_t a, uint4 v) {
    asm volatile("st.shared.v4.b32 [%0], {%1,%2,%3,%4};"
                 :: "r"(a), "r"(v.x), "r"(v.y), "r"(v.z), "r"(v.w));
}
__device__ __forceinline__ void cpa16(uint32_t saddr, const void* g) {
    asm volatile("cp.async.cg.shared.global [%0], [%1], 16;"
                 :: "r"(saddr), "l"(g));
}
#define CPA_COMMIT() asm volatile("cp.async.commit_group;")
#define CPA_WAIT0()  asm volatile("cp.async.wait_group 0;" ::: "memory")

__device__ __forceinline__ uint32_t pk(float lo, float hi) {
    uint32_t l = __bfloat16_as_ushort(__float2bfloat16(lo));
    uint32_t h = __bfloat16_as_ushort(__float2bfloat16(hi));
    return l | (h << 16);
}
__device__ __forceinline__ float ubf_lo(uint32_t v) {
    return __bfloat162float(__ushort_as_bfloat16((unsigned short)(v & 0xFFFF)));
}
__device__ __forceinline__ float ubf_hi(uint32_t v) {
    return __bfloat162float(__ushort_as_bfloat16((unsigned short)(v >> 16)));
}
__device__ __forceinline__ float siluf(float v) { return v / (1.f + __expf(-v)); }

__device__ __forceinline__ void mma_bf16(float* c,
                                         uint32_t a0, uint32_t a1, uint32_t a2, uint32_t a3,
                                         uint32_t b0, uint32_t b1) {
    asm volatile("mma.sync.aligned.m16n8k16.row.col.f32.bf16.bf16.f32 "
                 "{%0,%1,%2,%3}, {%4,%5,%6,%7}, {%8,%9}, {%0,%1,%2,%3};"
                 : "+f"(c[0]), "+f"(c[1]), "+f"(c[2]), "+f"(c[3])
                 : "r"(a0), "r"(a1), "r"(a2), "r"(a3), "r"(b0), "r"(b1));
}
__device__ __forceinline__ void ldsm4(uint32_t a, uint32_t& r0, uint32_t& r1,
                                      uint32_t& r2, uint32_t& r3) {
    asm volatile("ldmatrix.sync.aligned.m8n8.x4.shared.b16 {%0,%1,%2,%3}, [%4];"
                 : "=r"(r0), "=r"(r1), "=r"(r2), "=r"(r3) : "r"(a));
}

// warp tile 32(m) x 32(n); A rows m, B rows n, row-major over k, stride ld bytes.
__device__ __forceinline__ void warp_gemm32(uint32_t aAddr, uint32_t bAddr,
                                            uint32_t ld, int ksteps, float c[2][4][4]) {
    const uint32_t mstep = 16u * ld;
#pragma unroll 2
    for (int ks = 0; ks < ksteps; ks++) {
        uint32_t A[2][4], B[2][4];
        ldsm4(aAddr,         A[0][0], A[0][1], A[0][2], A[0][3]);
        ldsm4(aAddr + mstep, A[1][0], A[1][1], A[1][2], A[1][3]);
        ldsm4(bAddr,         B[0][0], B[0][1], B[0][2], B[0][3]);
        ldsm4(bAddr + mstep, B[1][0], B[1][1], B[1][2], B[1][3]);
        aAddr += 32; bAddr += 32;
#pragma unroll
        for (int mt = 0; mt < 2; mt++)
#pragma unroll
            for (int nt = 0; nt < 4; nt++)
                mma_bf16(c[mt][nt],
                         A[mt][0], A[mt][1], A[mt][2], A[mt][3],
                         B[nt >> 1][(nt & 1) * 2], B[nt >> 1][(nt & 1) * 2 + 1]);
    }
}
__device__ __forceinline__ void zero_c(float c[2][4][4]) {
#pragma unroll
    for (int i = 0; i < 2; i++)
#pragma unroll
        for (int j = 0; j < 4; j++)
#pragma unroll
            for (int k = 0; k < 4; k++) c[i][j][k] = 0.f;
}

// ---------------------------------------------------------------------------
__global__ void egnn_init_kernel(const float* __restrict__ x, float* __restrict__ x_out) {
    int i = blockIdx.x * blockDim.x + threadIdx.x;
    int s = gridDim.x * blockDim.x;
    for (int j = i; j < NN * HIDD; j += s) g_mi[j] = 0.f;
    for (int j = i; j < NN * 3;   j += s) x_out[j] = x[j];
}

// weights -> bf16, transposed [n][k] padded
__global__ void egnn_prep_kernel(const float* __restrict__ em_w1, const float* __restrict__ em_w2,
                                 const float* __restrict__ xm_w1, const float* __restrict__ nm_w1,
                                 const float* __restrict__ nm_w2) {
    const int TB = 7 * WTILE;
    const int TOT = TB + 128 * LDF;
    int i = blockIdx.x * blockDim.x + threadIdx.x;
    int s = gridDim.x * blockDim.x;
    for (int p = i; p < TOT; p += s) {
        if (p < TB) {
            int which = p / WTILE, pl = p % WTILE;
            int n = pl / LD2, k = pl % LD2;
            float v = 0.f;
            if (k < 128) {
                switch (which) {
                    case 0: v = em_w1[(size_t)k * 128 + n]; break;
                    case 1: v = em_w1[(size_t)(128 + k) * 128 + n]; break;
                    case 2: v = em_w2[(size_t)k * 128 + n]; break;
                    case 3: v = xm_w1[(size_t)k * 128 + n]; break;
                    case 4: v = nm_w1[(size_t)k * 128 + n]; break;
                    case 5: v = nm_w1[(size_t)(128 + k) * 128 + n]; break;
                    default: v = nm_w2[(size_t)k * 128 + n]; break;
                }
            }
            __nv_bfloat16* dst[7] = {g_w1at, g_w1bt, g_w2t, g_xw1t, g_nw1at, g_nw1bt, g_nw2t};
            dst[which][pl] = __float2bfloat16(v);
        } else {
            int pl = p - TB;
            int n = pl / LDF, k = pl % LDF;
            float v = (k < EF + 1) ? em_w1[(size_t)(256 + k) * 128 + n] : 0.f;
            g_w1ct[pl] = __float2bfloat16(v);
        }
    }
}

// ---------------------------------------------------------------------------
// Precompute: Pa = h@W1a, Pb = h@W1b, Ph = h@nm_w1[128:], fp32 out.
// ---------------------------------------------------------------------------
__global__ void __launch_bounds__(NT, 2) egnn_pre_kernel(const float* __restrict__ h) {
    extern __shared__ unsigned char sm[];
    const uint32_t sb = smem_u32(sm);
    const int tid  = threadIdx.x;
    const int wid  = tid >> 5;
    const int lane = tid & 31;
    const int gid  = lane >> 2;
    const int tig  = lane & 3;
    const int m0   = (wid >> 2) * 32;
    const int n0   = (wid & 3) * 32;
    const int nb   = blockIdx.x * ME;

    for (int q = tid; q < WBYTES / 16; q += NT)
        cpa16(sb + NW_OFF + q * 16, (const unsigned char*)g_w1at + q * 16);
    CPA_COMMIT();

    // gather h rows (bf16)
    for (int q = tid; q < ME * 16; q += NT) {
        int e = q >> 4, ch = q & 15;
        int n = nb + e;
        uint4 w = make_uint4(0, 0, 0, 0);
        if (n < NN) {
            const float4* sp = (const float4*)(h + (size_t)n * HIDD + ch * 8);
            float4 v0 = sp[0], v1 = sp[1];
            w.x = pk(v0.x, v0.y); w.y = pk(v0.z, v0.w);
            w.z = pk(v1.x, v1.y); w.w = pk(v1.z, v1.w);
        }
        sts128(sb + NA_OFF + (uint32_t)(e * LD2 + ch * 8) * 2, w);
    }
    CPA_WAIT0();
    __syncthreads();

    const uint32_t aOff = (uint32_t)(m0 + (lane & 15)) * (LD2 * 2) + ((lane >> 4) << 4);
    const uint32_t bOff = (uint32_t)(n0 + (lane & 7) + ((lane >> 4) << 3)) * (LD2 * 2)
                        + (((lane >> 3) & 1) << 4);
    float c[2][4][4];

#pragma unroll 1
    for (int t = 0; t < 3; t++) {
        zero_c(c);
        warp_gemm32(sb + NA_OFF + aOff, sb + NW_OFF + bOff, LD2 * 2, 8, c);
        __syncthreads();   // all warps done with current W
        if (t < 2) {
            const unsigned char* nw = (t == 0) ? (const unsigned char*)g_w1bt
                                               : (const unsigned char*)g_nw1bt;
            for (int q = tid; q < WBYTES / 16; q += NT)
                cpa16(sb + NW_OFF + q * 16, nw + q * 16);
            CPA_COMMIT();
        }
        float* P = (t == 0) ? g_pa : (t == 1) ? g_pb : g_ph;
#pragma unroll
        for (int mt = 0; mt < 2; mt++)
#pragma unroll
            for (int nt = 0; nt < 4; nt++) {
                int row = m0 + mt * 16 + gid;
                int col = n0 + nt * 8 + tig * 2;
                float* cc = c[mt][nt];
                int na = nb + row, na2 = nb + row + 8;
                if (na < NN)
                    *(float2*)(P + (size_t)na * HIDD + col) = make_float2(cc[0], cc[1]);
                if (na2 < NN)
                    *(float2*)(P + (size_t)na2 * HIDD + col) = make_float2(cc[2], cc[3]);
            }
        if (t < 2) { CPA_WAIT0(); __syncthreads(); }
    }
}

// ---------------------------------------------------------------------------
// Edge kernel: Psum gather + feat GEMM (K=32) + GEMM2 + GEMM3.
// ---------------------------------------------------------------------------
__global__ void __launch_bounds__(NT, 2) egnn_edge_kernel(
    const float* __restrict__ x,
    const int*   __restrict__ eidx,  const float* __restrict__ eattr,
    const float* __restrict__ em_b1, const float* __restrict__ em_b2,
    const float* __restrict__ ei_w,  const float* __restrict__ ei_b,
    const float* __restrict__ xm_b1, const float* __restrict__ xm_w2,
    float* __restrict__ x_out)
{
    extern __shared__ unsigned char sm[];
    const uint32_t sb = smem_u32(sm);
    const int tid  = threadIdx.x;
    const int wid  = tid >> 5;
    const int lane = tid & 31;
    const int gid  = lane >> 2;
    const int tig  = lane & 3;
    const int m0   = (wid >> 2) * 32;
    const int n0   = (wid & 3) * 32;
    const int e0   = blockIdx.x * ME;

    float* sB1  = (float*)(sm + OFF_B1);
    float* sB2  = (float*)(sm + OFF_B2);
    float* sEIW = (float*)(sm + OFF_EIW);
    float* sXB1 = (float*)(sm + OFF_XB1);
    float* sXW2 = (float*)(sm + OFF_XW2);
    float* sDsq = (float*)(sm + OFF_DSQ);
    float* sEij = (float*)(sm + OFF_EIJ);
    float* sRlX = (float*)(sm + OFF_RLX);
    float* sRlY = (float*)(sm + OFF_RLY);
    float* sRlZ = (float*)(sm + OFF_RLZ);
    int*   sDst = (int*)  (sm + OFF_DST);
    int*   sSrc = (int*)  (sm + OFF_SRC);
    float* sPart= (float*)(sm + OFF_PART);

    // async: W1c feat weights
    for (int q = tid; q < FBYTES / 16; q += NT)
        cpa16(sb + FW_OFF + q * 16, (const unsigned char*)g_w1ct + q * 16);
    CPA_COMMIT();

    if (tid < 128) {
        sB1[tid]  = em_b1[tid]; sB2[tid] = em_b2[tid]; sEIW[tid] = ei_w[tid];
        sXB1[tid] = xm_b1[tid]; sXW2[tid] = xm_w2[tid];
        int e  = e0 + tid;
        int s_ = eidx[e], d_ = eidx[NE + e];
        sSrc[tid] = s_; sDst[tid] = d_;
        float rx = x[d_ * 3 + 0] - x[s_ * 3 + 0];
        float ry = x[d_ * 3 + 1] - x[s_ * 3 + 1];
        float rz = x[d_ * 3 + 2] - x[s_ * 3 + 2];
        sRlX[tid] = rx; sRlY[tid] = ry; sRlZ[tid] = rz;
        sDsq[tid] = rx * rx + ry * ry + rz * rz;
    }
    __syncthreads();

    // gather Psum = Pa[dst] + Pb[src]  (fp32 add -> bf16) -> R1
    for (int q = tid; q < ME * 16; q += NT) {
        int e = q >> 4, ch = q & 15;
        const float4* pa = (const float4*)(g_pa + (size_t)sDst[e] * HIDD + ch * 8);
        const float4* pb = (const float4*)(g_pb + (size_t)sSrc[e] * HIDD + ch * 8);
        float4 a0 = pa[0], a1 = pa[1], b0 = pb[0], b1 = pb[1];
        uint4 w;
        w.x = pk(a0.x + b0.x, a0.y + b0.y); w.y = pk(a0.z + b0.z, a0.w + b0.w);
        w.z = pk(a1.x + b1.x, a1.y + b1.y); w.w = pk(a1.z + b1.z, a1.w + b1.w);
        sts128(sb + R1_OFF + (uint32_t)(e * LD2 + ch * 8) * 2, w);
    }
    // feat tile [128][LDF]: [dsq | eattr | 0]
    for (int q = tid; q < ME * (LDF / 8); q += NT) {
        int e = q / (LDF / 8), ch = q % (LDF / 8);
        int c0 = ch * 8;
        float v[8];
#pragma unroll
        for (int j = 0; j < 8; j++) {
            int k = c0 + j;
            float f = 0.f;
            if (k == 0) f = sDsq[e];
            else if (k <= EF) f = eattr[(size_t)(e0 + e) * EF + (k - 1)];
            v[j] = f;
        }
        uint4 w;
        w.x = pk(v[0], v[1]); w.y = pk(v[2], v[3]);
        w.z = pk(v[4], v[5]); w.w = pk(v[6], v[7]);
        sts128(sb + FA_OFF + (uint32_t)(e * LDF + c0) * 2, w);
    }
    CPA_WAIT0();
    __syncthreads();

    float c[2][4][4];
    const uint32_t aOffF = (uint32_t)(m0 + (lane & 15)) * (LDF * 2) + ((lane >> 4) << 4);
    const uint32_t bOffF = (uint32_t)(n0 + (lane & 7) + ((lane >> 4) << 3)) * (LDF * 2)
                         + (((lane >> 3) & 1) << 4);
    const uint32_t aOff2 = (uint32_t)(m0 + (lane & 15)) * (LD2 * 2) + ((lane >> 4) << 4);
    const uint32_t bOff2 = (uint32_t)(n0 + (lane & 7) + ((lane >> 4) << 3)) * (LD2 * 2)
                         + (((lane >> 3) & 1) << 4);

    // ---- feat GEMM: C = featA @ W1c (K=32) ----
    zero_c(c);
    warp_gemm32(sb + FA_OFF + aOffF, sb + FW_OFF + bOffF, LDF * 2, 2, c);
    __syncthreads();   // feat tiles no longer needed

    // async: W2t into R3
    for (int q = tid; q < WBYTES / 16; q += NT)
        cpa16(sb + R3_OFF + q * 16, (const unsigned char*)g_w2t + q * 16);
    CPA_COMMIT();

    // epilogue1: S = silu(Cfeat + Psum + b1) -> R2
#pragma unroll
    for (int mt = 0; mt < 2; mt++)
#pragma unroll
        for (int nt = 0; nt < 4; nt++) {
            int row = m0 + mt * 16 + gid;
            int col = n0 + nt * 8 + tig * 2;
            float* cc = c[mt][nt];
            uint32_t p0 = lds32(sb + R1_OFF + (uint32_t)(row * LD2 + col) * 2);
            uint32_t p1 = lds32(sb + R1_OFF + (uint32_t)((row + 8) * LD2 + col) * 2);
            sts32(sb + R2_OFF + (uint32_t)(row * LD2 + col) * 2,
                  pk(siluf(cc[0] + ubf_lo(p0) + sB1[col]),
                     siluf(cc[1] + ubf_hi(p0) + sB1[col + 1])));
            sts32(sb + R2_OFF + (uint32_t)((row + 8) * LD2 + col) * 2,
                  pk(siluf(cc[2] + ubf_lo(p1) + sB1[col]),
                     siluf(cc[3] + ubf_hi(p1) + sB1[col + 1])));
        }
    CPA_WAIT0();
    __syncthreads();

    // ---- GEMM2: mij = S @ W2 + b2 -> M (R1) ; eij partial dot ----
    zero_c(c);
    warp_gemm32(sb + R2_OFF + aOff2, sb + R3_OFF + bOff2, LD2 * 2, 8, c);
    {
        float p[2][2] = {{0.f, 0.f}, {0.f, 0.f}};
#pragma unroll
        for (int mt = 0; mt < 2; mt++)
#pragma unroll
            for (int nt = 0; nt < 4; nt++) {
                int row = m0 + mt * 16 + gid;
                int col = n0 + nt * 8 + tig * 2;
                float* cc = c[mt][nt];
                float v0 = cc[0] + sB2[col], v1 = cc[1] + sB2[col + 1];
                float v2 = cc[2] + sB2[col], v3 = cc[3] + sB2[col + 1];
                sts32(sb + R1_OFF + (uint32_t)(row * LD2 + col) * 2, pk(v0, v1));
                sts32(sb + R1_OFF + (uint32_t)((row + 8) * LD2 + col) * 2, pk(v2, v3));
                p[mt][0] += v0 * sEIW[col] + v1 * sEIW[col + 1];
                p[mt][1] += v2 * sEIW[col] + v3 * sEIW[col + 1];
            }
#pragma unroll
        for (int mt = 0; mt < 2; mt++)
#pragma unroll
            for (int hh = 0; hh < 2; hh++) {
                float v = p[mt][hh];
                v += __shfl_xor_sync(0xffffffffu, v, 1);
                v += __shfl_xor_sync(0xffffffffu, v, 2);
                if (tig == 0)
                    sPart[(wid & 3) * 128 + m0 + mt * 16 + hh * 8 + gid] = v;
            }
    }
    __syncthreads();   // GEMM2 done reading R3; M + partials visible

    // async: XW1t into R3
    for (int q = tid; q < WBYTES / 16; q += NT)
        cpa16(sb + R3_OFF + q * 16, (const unsigned char*)g_xw1t + q * 16);
    CPA_COMMIT();

    if (tid < 128) {
        float t = sPart[tid] + sPart[128 + tid] + sPart[256 + tid] + sPart[384 + tid]
                + ei_b[0];
        sEij[tid] = 1.f / (1.f + __expf(-t));
    }
    __syncthreads();

    // ---- scatter: g_mi[dst] += mij * eij ----
    for (int q = tid; q < ME * 32; q += NT) {
        int e = q >> 5, c4 = (q & 31) * 4;
        const uint32_t* mp = (const uint32_t*)(sm + R1_OFF + (uint32_t)(e * LD2 + c4) * 2);
        uint32_t u0 = mp[0], u1 = mp[1];
        float ei = sEij[e];
        float v0 = ubf_lo(u0) * ei, v1 = ubf_hi(u0) * ei;
        float v2 = ubf_lo(u1) * ei, v3 = ubf_hi(u1) * ei;
        float* g = g_mi + (size_t)sDst[e] * HIDD + c4;
        asm volatile("red.global.add.v4.f32 [%0], {%1,%2,%3,%4};"
                     :: "l"(g), "f"(v0), "f"(v1), "f"(v2), "f"(v3) : "memory");
    }
    CPA_WAIT0();
    __syncthreads();

    // ---- GEMM3: u = silu(M @ xm_w1 + xb1); gate dot ----
    zero_c(c);
    warp_gemm32(sb + R1_OFF + aOff2, sb + R3_OFF + bOff2, LD2 * 2, 8, c);
    {
        float p[2][2] = {{0.f, 0.f}, {0.f, 0.f}};
#pragma unroll
        for (int mt = 0; mt < 2; mt++)
#pragma unroll
            for (int nt = 0; nt < 4; nt++) {
                int col = n0 + nt * 8 + tig * 2;
                float* cc = c[mt][nt];
                p[mt][0] += siluf(cc[0] + sXB1[col]) * sXW2[col]
                          + siluf(cc[1] + sXB1[col + 1]) * sXW2[col + 1];
                p[mt][1] += siluf(cc[2] + sXB1[col]) * sXW2[col]
                          + siluf(cc[3] + sXB1[col + 1]) * sXW2[col + 1];
            }
#pragma unroll
        for (int mt = 0; mt < 2; mt++)
#pragma unroll
            for (int hh = 0; hh < 2; hh++) {
                float v = p[mt][hh];
                v += __shfl_xor_sync(0xffffffffu, v, 1);
                v += __shfl_xor_sync(0xffffffffu, v, 2);
                if (tig == 0)
                    sPart[(wid & 3) * 128 + m0 + mt * 16 + hh * 8 + gid] = v;
            }
    }
    __syncthreads();

    if (tid < 128) {
        float g = tanhf(sPart[tid] + sPart[128 + tid] + sPart[256 + tid] + sPart[384 + tid]);
        float coef = g / (sqrtf(sDsq[tid] + 1e-8f) + 1.f);
        int d = sDst[tid];
        atomicAdd(&x_out[d * 3 + 0], sRlX[tid] * coef);
        atomicAdd(&x_out[d * 3 + 1], sRlY[tid] * coef);
        atomicAdd(&x_out[d * 3 + 2], sRlZ[tid] * coef);
    }
}

// ---------------------------------------------------------------------------
// Node kernel: h_out = h + nm2(silu(mi@nm_w1a + Ph + b1)) + ... (K=128 GEMMs)
// ---------------------------------------------------------------------------
__global__ void __launch_bounds__(NT, 2) egnn_node_kernel(
    const float* __restrict__ h,
    const float* __restrict__ nm_b1, const float* __restrict__ nm_b2,
    float* __restrict__ h_out)
{
    extern __shared__ unsigned char sm[];
    const uint32_t sb = smem_u32(sm);
    const int tid  = threadIdx.x;
    const int wid  = tid >> 5;
    const int lane = tid & 31;
    const int gid  = lane >> 2;
    const int tig  = lane & 3;
    const int m0   = (wid >> 2) * 32;
    const int n0   = (wid & 3) * 32;
    const int nb   = blockIdx.x * ME;

    float* sB1 = (float*)(sm + OFF_B1);
    float* sB2 = (float*)(sm + OFF_B2);

    for (int q = tid; q < WBYTES / 16; q += NT)
        cpa16(sb + NW_OFF + q * 16, (const unsigned char*)g_nw1at + q * 16);
    CPA_COMMIT();

    if (tid < 128) { sB1[tid] = nm_b1[tid]; sB2[tid] = nm_b2[tid]; }

    // gather mi rows (bf16)
    for (int q = tid; q < ME * 16; q += NT) {
        int e = q >> 4, ch = q & 15;
        int n = nb + e;
        uint4 w = make_uint4(0, 0, 0, 0);
        if (n < NN) {
            const float4* sp = (const float4*)(g_mi + (size_t)n * HIDD + ch * 8);
            float4 v0 = sp[0], v1 = sp[1];
            w.x = pk(v0.x, v0.y); w.y = pk(v0.z, v0.w);
            w.z = pk(v1.x, v1.y); w.w = pk(v1.z, v1.w);
        }
        sts128(sb + NA_OFF + (uint32_t)(e * LD2 + ch * 8) * 2, w);
    }
    CPA_WAIT0();
    __syncthreads();

    const uint32_t aOff = (uint32_t)(m0 + (lane & 15)) * (LD2 * 2) + ((lane >> 4) << 4);
    const uint32_t bOff = (uint32_t)(n0 + (lane & 7) + ((lane >> 4) << 3)) * (LD2 * 2)
                        + (((lane >> 3) & 1) << 4);
    float c[2][4][4];

    // GEMM1: C = mi @ nm_w1a
    zero_c(c);
    warp_gemm32(sb + NA_OFF + aOff, sb + NW_OFF + bOff, LD2 * 2, 8, c);
    __syncthreads();   // A + W readers done

    for (int q = tid; q < WBYTES / 16; q += NT)
        cpa16(sb + NW_OFF + q * 16, (const unsigned char*)g_nw2t + q * 16);
    CPA_COMMIT();

    // epilogue1: S = silu(C + Ph + b1) -> A region
#pragma unroll
    for (int mt = 0; mt < 2; mt++)
#pragma unroll
        for (int nt = 0; nt < 4; nt++) {
            int row = m0 + mt * 16 + gid;
            int col = n0 + nt * 8 + tig * 2;
            float* cc = c[mt][nt];
            int na = nb + row, na2 = nb + row + 8;
            float2 p0 = make_float2(0.f, 0.f), p1 = make_float2(0.f, 0.f);
            if (na < NN)  p0 = *(const float2*)(g_ph + (size_t)na * HIDD + col);
            if (na2 < NN) p1 = *(const float2*)(g_ph + (size_t)na2 * HIDD + col);
            sts32(sb + NA_OFF + (uint32_t)(row * LD2 + col) * 2,
                  pk(siluf(cc[0] + p0.x + sB1[col]), siluf(cc[1] + p0.y + sB1[col + 1])));
            sts32(sb + NA_OFF + (uint32_t)((row + 8) * LD2 + col) * 2,
                  pk(siluf(cc[2] + p1.x + sB1[col]), siluf(cc[3] + p1.y + sB1[col + 1])));
        }
    CPA_WAIT0();
    __syncthreads();

    // GEMM2 + residual epilogue
    zero_c(c);
    warp_gemm32(sb + NA_OFF + aOff, sb + NW_OFF + bOff, LD2 * 2, 8, c);

#pragma unroll
    for (int mt = 0; mt < 2; mt++)
#pragma unroll
        for (int nt = 0; nt < 4; nt++) {
            int row = m0 + mt * 16 + gid;
            int col = n0 + nt * 8 + tig * 2;
            float* cc = c[mt][nt];
            int na = nb + row, na2 = nb + row + 8;
            if (na < NN) {
                const float2 hv = *(const float2*)(h + (size_t)na * HIDD + col);
                *(float2*)(h_out + (size_t)na * HIDD + col) =
                    make_float2(cc[0] + sB2[col] + hv.x, cc[1] + sB2[col + 1] + hv.y);
            }
            if (na2 < NN) {
                const float2 hv = *(const float2*)(h + (size_t)na2 * HIDD + col);
                *(float2*)(h_out + (size_t)na2 * HIDD + col) =
                    make_float2(cc[2] + sB2[col] + hv.x, cc[3] + sB2[col + 1] + hv.y);
            }
        }
}

// ---------------------------------------------------------------------------
extern "C" void kernel_launch(void* const* d_in, const int* in_sizes, int n_in,
                              void* d_out, int out_size) {
    const float* h     = (const float*)d_in[0];
    const float* x     = (const float*)d_in[1];
    const int*   eidx  = (const int*)  d_in[2];
    const float* eattr = (const float*)d_in[3];
    const float* em_w1 = (const float*)d_in[4];
    const float* em_b1 = (const float*)d_in[5];
    const float* em_w2 = (const float*)d_in[6];
    const float* em_b2 = (const float*)d_in[7];
    const float* ei_w  = (const float*)d_in[8];
    const float* ei_b  = (const float*)d_in[9];
    const float* xm_w1 = (const float*)d_in[10];
    const float* xm_b1 = (const float*)d_in[11];
    const float* xm_w2 = (const float*)d_in[12];
    const float* nm_w1 = (const float*)d_in[13];
    const float* nm_b1 = (const float*)d_in[14];
    const float* nm_w2 = (const float*)d_in[15];
    const float* nm_b2 = (const float*)d_in[16];

    float* out   = (float*)d_out;
    float* h_out = out;                        // [NN, 128]
    float* x_out = out + (size_t)NN * HIDD;    // [NN, 3]

    cudaFuncSetAttribute(egnn_edge_kernel,
                         cudaFuncAttributeMaxDynamicSharedMemorySize, EDGE_SMEM);
    cudaFuncSetAttribute(egnn_node_kernel,
                         cudaFuncAttributeMaxDynamicSharedMemorySize, NODE_SMEM);
    cudaFuncSetAttribute(egnn_pre_kernel,
                         cudaFuncAttributeMaxDynamicSharedMemorySize, NODE_SMEM);

    egnn_init_kernel<<<1024, 256>>>(x, x_out);
    egnn_prep_kernel<<<128, 256>>>(em_w1, em_w2, xm_w1, nm_w1, nm_w2);
    egnn_pre_kernel<<<(NN + ME - 1) / ME, NT, NODE_SMEM>>>(h);
    egnn_edge_kernel<<<NE / ME, NT, EDGE_SMEM>>>(
        x, eidx, eattr, em_b1, em_b2, ei_w, ei_b, xm_b1, xm_w2, x_out);
    egnn_node_kernel<<<(NN + ME - 1) / ME, NT, NODE_SMEM>>>(
        h, nm_b1, nm_b2, h_out);
}

// round 9
// speedup vs baseline: 10.1829x; 1.0095x over previous
#include <cuda_runtime.h>
#include <cuda_bf16.h>
#include <cstdint>

#define NN   50000
#define NE   640000
#define HIDD 128
#define EF   16
#define LD2  136          // elems; 272 B row stride (K=128 tiles)
#define LDF  40           // feat tiles: 80 B row stride (K=32)
#define ME   128          // rows per CTA
#define NT   512          // 16 warps

#define WTILE (128 * LD2)             // 17408 elems / 34816 B
#define WBYTES 34816
#define FBYTES (128 * LDF * 2)        // 10240

// ---- edge kernel smem (bytes) ----
#define OFF_WEI  0
#define OFF_B2   512
#define OFF_XW2  1024
#define OFF_B23  1536
#define OFF_DSQ  2048
#define OFF_EIJ  2560
#define OFF_RLX  3072
#define OFF_RLY  3584
#define OFF_RLZ  4096
#define OFF_DST  4608
#define OFF_SRC  5120
#define OFF_PART 5632                 // fp32[512] -> ends 7680
#define R1_OFF   8192                 // Psum -> S in place  [128][LD2] bf16
#define RW2_OFF  (R1_OFF + WBYTES)    // W2t
#define RW23_OFF (RW2_OFF + WBYTES)   // featA+featW early, then W23t
#define FA_OFF   RW23_OFF
#define FW_OFF   (RW23_OFF + FBYTES)
#define EDGE_SMEM (RW23_OFF + WBYTES) // 112640

// ---- node / pre kernels ----
#define NA_OFF   1024
#define NW_OFF   (NA_OFF + WBYTES)
#define NODE_SMEM (NW_OFF + WBYTES)   // 70656

__device__ float    g_mi[(size_t)NN * HIDD];
__device__ uint32_t g_pa16[(size_t)NN * 64];   // Pa bf16-packed
__device__ uint32_t g_pb16[(size_t)NN * 64];   // Pb bf16-packed
__device__ float    g_ph[(size_t)NN * HIDD];
__device__ float    g_wei[HIDD];
__device__ float    g_b23[HIDD];
__device__ float    g_cei;
__device__ __align__(16) __nv_bfloat16 g_w1at [WTILE];
__device__ __align__(16) __nv_bfloat16 g_w1bt [WTILE];
__device__ __align__(16) __nv_bfloat16 g_w1ct [128 * LDF];
__device__ __align__(16) __nv_bfloat16 g_w2t  [WTILE];
__device__ __align__(16) __nv_bfloat16 g_w23t [WTILE];
__device__ __align__(16) __nv_bfloat16 g_nw1at[WTILE];
__device__ __align__(16) __nv_bfloat16 g_nw1bt[WTILE];
__device__ __align__(16) __nv_bfloat16 g_nw2t [WTILE];

// ---------------------------------------------------------------------------
__device__ __forceinline__ uint32_t smem_u32(const void* p) {
    uint32_t a;
    asm("{ .reg .u64 t; cvta.to.shared.u64 t, %1; cvt.u32.u64 %0, t; }"
        : "=r"(a) : "l"(p));
    return a;
}
__device__ __forceinline__ uint32_t lds32(uint32_t a) {
    uint32_t v;
    asm volatile("ld.shared.b32 %0, [%1];" : "=r"(v) : "r"(a));
    return v;
}
__device__ __forceinline__ void sts32(uint32_t a, uint32_t v) {
    asm volatile("st.shared.b32 [%0], %1;" :: "r"(a), "r"(v));
}
__device__ __forceinline__ void sts128(uint32_t a, uint4 v) {
    asm volatile("st.shared.v4.b32 [%0], {%1,%2,%3,%4};"
                 :: "r"(a), "r"(v.x), "r"(v.y), "r"(v.z), "r"(v.w));
}
__device__ __forceinline__ void cpa16(uint32_t saddr, const void* g) {
    asm volatile("cp.async.cg.shared.global [%0], [%1], 16;"
                 :: "r"(saddr), "l"(g));
}
#define CPA_COMMIT() asm volatile("cp.async.commit_group;")
#define CPA_WAIT0()  asm volatile("cp.async.wait_group 0;" ::: "memory")

__device__ __forceinline__ uint32_t pk(float lo, float hi) {
    uint32_t l = __bfloat16_as_ushort(__float2bfloat16(lo));
    uint32_t h = __bfloat16_as_ushort(__float2bfloat16(hi));
    return l | (h << 16);
}
__device__ __forceinline__ float ubf_lo(uint32_t v) {
    return __bfloat162float(__ushort_as_bfloat16((unsigned short)(v & 0xFFFF)));
}
__device__ __forceinline__ float ubf_hi(uint32_t v) {
    return __bfloat162float(__ushort_as_bfloat16((unsigned short)(v >> 16)));
}
__device__ __forceinline__ uint32_t hadd2u(uint32_t a, uint32_t b) {
    __nv_bfloat162 r = __hadd2(*(__nv_bfloat162*)&a, *(__nv_bfloat162*)&b);
    return *(uint32_t*)&r;
}
__device__ __forceinline__ float siluf(float v) { return v / (1.f + __expf(-v)); }

__device__ __forceinline__ void mma_bf16(float* c,
                                         uint32_t a0, uint32_t a1, uint32_t a2, uint32_t a3,
                                         uint32_t b0, uint32_t b1) {
    asm volatile("mma.sync.aligned.m16n8k16.row.col.f32.bf16.bf16.f32 "
                 "{%0,%1,%2,%3}, {%4,%5,%6,%7}, {%8,%9}, {%0,%1,%2,%3};"
                 : "+f"(c[0]), "+f"(c[1]), "+f"(c[2]), "+f"(c[3])
                 : "r"(a0), "r"(a1), "r"(a2), "r"(a3), "r"(b0), "r"(b1));
}
__device__ __forceinline__ void ldsm4(uint32_t a, uint32_t& r0, uint32_t& r1,
                                      uint32_t& r2, uint32_t& r3) {
    asm volatile("ldmatrix.sync.aligned.m8n8.x4.shared.b16 {%0,%1,%2,%3}, [%4];"
                 : "=r"(r0), "=r"(r1), "=r"(r2), "=r"(r3) : "r"(a));
}

// warp tile 32(m) x 32(n)
__device__ __forceinline__ void warp_gemm32(uint32_t aAddr, uint32_t bAddr,
                                            uint32_t ld, int ksteps, float c[2][4][4]) {
    const uint32_t mstep = 16u * ld;
#pragma unroll 2
    for (int ks = 0; ks < ksteps; ks++) {
        uint32_t A[2][4], B[2][4];
        ldsm4(aAddr,         A[0][0], A[0][1], A[0][2], A[0][3]);
        ldsm4(aAddr + mstep, A[1][0], A[1][1], A[1][2], A[1][3]);
        ldsm4(bAddr,         B[0][0], B[0][1], B[0][2], B[0][3]);
        ldsm4(bAddr + mstep, B[1][0], B[1][1], B[1][2], B[1][3]);
        aAddr += 32; bAddr += 32;
#pragma unroll
        for (int mt = 0; mt < 2; mt++)
#pragma unroll
            for (int nt = 0; nt < 4; nt++)
                mma_bf16(c[mt][nt],
                         A[mt][0], A[mt][1], A[mt][2], A[mt][3],
                         B[nt >> 1][(nt & 1) * 2], B[nt >> 1][(nt & 1) * 2 + 1]);
    }
}
__device__ __forceinline__ void zero_c(float c[2][4][4]) {
#pragma unroll
    for (int i = 0; i < 2; i++)
#pragma unroll
        for (int j = 0; j < 4; j++)
#pragma unroll
            for (int k = 0; k < 4; k++) c[i][j][k] = 0.f;
}

// ---------------------------------------------------------------------------
__global__ void egnn_init_kernel(const float* __restrict__ x, float* __restrict__ x_out) {
    int i = blockIdx.x * blockDim.x + threadIdx.x;
    int s = gridDim.x * blockDim.x;
    for (int j = i; j < NN * HIDD; j += s) g_mi[j] = 0.f;
    for (int j = i; j < NN * 3;   j += s) x_out[j] = x[j];
}

// weights -> bf16 transposed [n][k]; plus fused matrices W23, w_ei, b23, c_ei
__global__ void egnn_prep_kernel(const float* __restrict__ em_w1, const float* __restrict__ em_w2,
                                 const float* __restrict__ xm_w1, const float* __restrict__ nm_w1,
                                 const float* __restrict__ nm_w2, const float* __restrict__ em_b1,
                                 const float* __restrict__ em_b2, const float* __restrict__ ei_w,
                                 const float* __restrict__ ei_b,  const float* __restrict__ xm_b1) {
    const int E6  = 6 * WTILE;
    const int C1  = E6 + 128 * LDF;
    const int W23 = C1 + WTILE;
    const int WEI = W23 + 128;
    const int B23 = WEI + 128;
    const int TOT = B23 + 1;
    int i = blockIdx.x * blockDim.x + threadIdx.x;
    int s = gridDim.x * blockDim.x;
    for (int p = i; p < TOT; p += s) {
        if (p < E6) {
            int which = p / WTILE, pl = p % WTILE;
            int n = pl / LD2, k = pl % LD2;
            float v = 0.f;
            if (k < 128) {
                switch (which) {
                    case 0: v = em_w1[(size_t)k * 128 + n]; break;
                    case 1: v = em_w1[(size_t)(128 + k) * 128 + n]; break;
                    case 2: v = em_w2[(size_t)k * 128 + n]; break;
                    case 3: v = nm_w1[(size_t)k * 128 + n]; break;
                    case 4: v = nm_w1[(size_t)(128 + k) * 128 + n]; break;
                    default: v = nm_w2[(size_t)k * 128 + n]; break;
                }
            }
            __nv_bfloat16* dst[6] = {g_w1at, g_w1bt, g_w2t, g_nw1at, g_nw1bt, g_nw2t};
            dst[which][pl] = __float2bfloat16(v);
        } else if (p < C1) {
            int pl = p - E6;
            int n = pl / LDF, k = pl % LDF;
            float v = 0.f;
            if (k < EF + 1)       v = em_w1[(size_t)(256 + k) * 128 + n];
            else if (k == EF + 1) v = em_b1[n];          // bias fold (ones column)
            g_w1ct[pl] = __float2bfloat16(v);
        } else if (p < W23) {
            int pl = p - C1;
            int n = pl / LD2, k = pl % LD2;
            float v = 0.f;
            if (k < 128) {
                for (int cidx = 0; cidx < 128; cidx++)
                    v += em_w2[(size_t)k * 128 + cidx] * xm_w1[(size_t)cidx * 128 + n];
            }
            g_w23t[pl] = __float2bfloat16(v);
        } else if (p < WEI) {
            int k = p - W23;
            float v = 0.f;
            for (int cidx = 0; cidx < 128; cidx++)
                v += em_w2[(size_t)k * 128 + cidx] * ei_w[cidx];
            g_wei[k] = v;
        } else if (p < B23) {
            int n = p - WEI;
            float v = xm_b1[n];
            for (int cidx = 0; cidx < 128; cidx++)
                v += em_b2[cidx] * xm_w1[(size_t)cidx * 128 + n];
            g_b23[n] = v;
        } else {
            float v = ei_b[0];
            for (int cidx = 0; cidx < 128; cidx++) v += em_b2[cidx] * ei_w[cidx];
            g_cei = v;
        }
    }
}

// ---------------------------------------------------------------------------
// Precompute: Pa = h@W1a (bf16), Pb = h@W1b (bf16), Ph = h@nm_w1[128:] (fp32)
// ---------------------------------------------------------------------------
__global__ void __launch_bounds__(NT, 2) egnn_pre_kernel(const float* __restrict__ h) {
    extern __shared__ unsigned char sm[];
    const uint32_t sb = smem_u32(sm);
    const int tid  = threadIdx.x;
    const int wid  = tid >> 5;
    const int lane = tid & 31;
    const int gid  = lane >> 2;
    const int tig  = lane & 3;
    const int m0   = (wid >> 2) * 32;
    const int n0   = (wid & 3) * 32;
    const int nb   = blockIdx.x * ME;

    for (int q = tid; q < WBYTES / 16; q += NT)
        cpa16(sb + NW_OFF + q * 16, (const unsigned char*)g_w1at + q * 16);
    CPA_COMMIT();

    for (int q = tid; q < ME * 16; q += NT) {
        int e = q >> 4, ch = q & 15;
        int n = nb + e;
        uint4 w = make_uint4(0, 0, 0, 0);
        if (n < NN) {
            const float4* sp = (const float4*)(h + (size_t)n * HIDD + ch * 8);
            float4 v0 = sp[0], v1 = sp[1];
            w.x = pk(v0.x, v0.y); w.y = pk(v0.z, v0.w);
            w.z = pk(v1.x, v1.y); w.w = pk(v1.z, v1.w);
        }
        sts128(sb + NA_OFF + (uint32_t)(e * LD2 + ch * 8) * 2, w);
    }
    CPA_WAIT0();
    __syncthreads();

    const uint32_t aOff = (uint32_t)(m0 + (lane & 15)) * (LD2 * 2) + ((lane >> 4) << 4);
    const uint32_t bOff = (uint32_t)(n0 + (lane & 7) + ((lane >> 4) << 3)) * (LD2 * 2)
                        + (((lane >> 3) & 1) << 4);
    float c[2][4][4];

#pragma unroll 1
    for (int t = 0; t < 3; t++) {
        zero_c(c);
        warp_gemm32(sb + NA_OFF + aOff, sb + NW_OFF + bOff, LD2 * 2, 8, c);
        __syncthreads();
        if (t < 2) {
            const unsigned char* nw = (t == 0) ? (const unsigned char*)g_w1bt
                                               : (const unsigned char*)g_nw1bt;
            for (int q = tid; q < WBYTES / 16; q += NT)
                cpa16(sb + NW_OFF + q * 16, nw + q * 16);
            CPA_COMMIT();
        }
#pragma unroll
        for (int mt = 0; mt < 2; mt++)
#pragma unroll
            for (int nt = 0; nt < 4; nt++) {
                int row = m0 + mt * 16 + gid;
                int col = n0 + nt * 8 + tig * 2;
                float* cc = c[mt][nt];
                int na = nb + row, na2 = nb + row + 8;
                if (t < 2) {
                    uint32_t* P16 = (t == 0) ? g_pa16 : g_pb16;
                    if (na  < NN) P16[(size_t)na  * 64 + (col >> 1)] = pk(cc[0], cc[1]);
                    if (na2 < NN) P16[(size_t)na2 * 64 + (col >> 1)] = pk(cc[2], cc[3]);
                } else {
                    if (na  < NN)
                        *(float2*)(g_ph + (size_t)na  * HIDD + col) = make_float2(cc[0], cc[1]);
                    if (na2 < NN)
                        *(float2*)(g_ph + (size_t)na2 * HIDD + col) = make_float2(cc[2], cc[3]);
                }
            }
        if (t < 2) { CPA_WAIT0(); __syncthreads(); }
    }
}

// ---------------------------------------------------------------------------
// Edge kernel: feat GEMM + epi1(S, eij) + GEMM2(scatter from regs) + GEMM3'
// ---------------------------------------------------------------------------
__global__ void __launch_bounds__(NT, 2) egnn_edge_kernel(
    const float* __restrict__ x,
    const int*   __restrict__ eidx,  const float* __restrict__ eattr,
    const float* __restrict__ em_b2, const float* __restrict__ xm_w2,
    float* __restrict__ x_out)
{
    extern __shared__ unsigned char sm[];
    const uint32_t sb = smem_u32(sm);
    const int tid  = threadIdx.x;
    const int wid  = tid >> 5;
    const int lane = tid & 31;
    const int gid  = lane >> 2;
    const int tig  = lane & 3;
    const int m0   = (wid >> 2) * 32;
    const int n0   = (wid & 3) * 32;
    const int e0   = blockIdx.x * ME;

    float* sWEI = (float*)(sm + OFF_WEI);
    float* sB2  = (float*)(sm + OFF_B2);
    float* sXW2 = (float*)(sm + OFF_XW2);
    float* sB23 = (float*)(sm + OFF_B23);
    float* sDsq = (float*)(sm + OFF_DSQ);
    float* sEij = (float*)(sm + OFF_EIJ);
    float* sRlX = (float*)(sm + OFF_RLX);
    float* sRlY = (float*)(sm + OFF_RLY);
    float* sRlZ = (float*)(sm + OFF_RLZ);
    int*   sDst = (int*)  (sm + OFF_DST);
    int*   sSrc = (int*)  (sm + OFF_SRC);
    float* sPart= (float*)(sm + OFF_PART);

    // async: feat weights + W2t (both needed before/at GEMM phases)
    for (int q = tid; q < FBYTES / 16; q += NT)
        cpa16(sb + FW_OFF + q * 16, (const unsigned char*)g_w1ct + q * 16);
    for (int q = tid; q < WBYTES / 16; q += NT)
        cpa16(sb + RW2_OFF + q * 16, (const unsigned char*)g_w2t + q * 16);
    CPA_COMMIT();

    if (tid < 128) {
        sWEI[tid] = g_wei[tid]; sB2[tid] = em_b2[tid];
        sXW2[tid] = xm_w2[tid]; sB23[tid] = g_b23[tid];
        int e  = e0 + tid;
        int s_ = eidx[e], d_ = eidx[NE + e];
        sSrc[tid] = s_; sDst[tid] = d_;
        float rx = x[d_ * 3 + 0] - x[s_ * 3 + 0];
        float ry = x[d_ * 3 + 1] - x[s_ * 3 + 1];
        float rz = x[d_ * 3 + 2] - x[s_ * 3 + 2];
        sRlX[tid] = rx; sRlY[tid] = ry; sRlZ[tid] = rz;
        sDsq[tid] = rx * rx + ry * ry + rz * rz;
    }
    __syncthreads();

    // gather Psum = Pa[dst] + Pb[src]  (bf16 HADD2) -> R1
    for (int q = tid; q < ME * 8; q += NT) {
        int e = q >> 3, ch = q & 7;
        const uint4* pa = (const uint4*)(g_pa16 + (size_t)sDst[e] * 64 + ch * 8);
        const uint4* pb = (const uint4*)(g_pb16 + (size_t)sSrc[e] * 64 + ch * 8);
        uint4 a0 = pa[0], a1 = pa[1], b0 = pb[0], b1 = pb[1];
        uint4 w0, w1;
        w0.x = hadd2u(a0.x, b0.x); w0.y = hadd2u(a0.y, b0.y);
        w0.z = hadd2u(a0.z, b0.z); w0.w = hadd2u(a0.w, b0.w);
        w1.x = hadd2u(a1.x, b1.x); w1.y = hadd2u(a1.y, b1.y);
        w1.z = hadd2u(a1.z, b1.z); w1.w = hadd2u(a1.w, b1.w);
        uint32_t base = sb + R1_OFF + (uint32_t)(e * LD2 + ch * 16) * 2;
        sts128(base, w0);
        sts128(base + 16, w1);
    }
    // feat tile [128][LDF]: [dsq | eattr | 1(bias) | 0]
    for (int q = tid; q < ME * (LDF / 8); q += NT) {
        int e = q / (LDF / 8), ch = q % (LDF / 8);
        int c0 = ch * 8;
        float v[8];
#pragma unroll
        for (int j = 0; j < 8; j++) {
            int k = c0 + j;
            float f = 0.f;
            if (k == 0) f = sDsq[e];
            else if (k <= EF) f = eattr[(size_t)(e0 + e) * EF + (k - 1)];
            else if (k == EF + 1) f = 1.f;
            v[j] = f;
        }
        uint4 w;
        w.x = pk(v[0], v[1]); w.y = pk(v[2], v[3]);
        w.z = pk(v[4], v[5]); w.w = pk(v[6], v[7]);
        sts128(sb + FA_OFF + (uint32_t)(e * LDF + c0) * 2, w);
    }
    CPA_WAIT0();
    __syncthreads();

    float c[2][4][4];
    const uint32_t aOffF = (uint32_t)(m0 + (lane & 15)) * (LDF * 2) + ((lane >> 4) << 4);
    const uint32_t bOffF = (uint32_t)(n0 + (lane & 7) + ((lane >> 4) << 3)) * (LDF * 2)
                         + (((lane >> 3) & 1) << 4);
    const uint32_t aOff2 = (uint32_t)(m0 + (lane & 15)) * (LD2 * 2) + ((lane >> 4) << 4);
    const uint32_t bOff2 = (uint32_t)(n0 + (lane & 7) + ((lane >> 4) << 3)) * (LD2 * 2)
                         + (((lane >> 3) & 1) << 4);

    // ---- feat GEMM (K=32, bias folded) ----
    zero_c(c);
    warp_gemm32(sb + FA_OFF + aOffF, sb + FW_OFF + bOffF, LDF * 2, 2, c);
    __syncthreads();   // feat region free

    // async: W23t into RW23 (overwrites feat area)
    for (int q = tid; q < WBYTES / 16; q += NT)
        cpa16(sb + RW23_OFF + q * 16, (const unsigned char*)g_w23t + q * 16);
    CPA_COMMIT();

    // ---- epilogue1: S = silu(Cfeat + Psum) in place; eij partials (S . w_ei)
    {
        float p[2][2] = {{0.f, 0.f}, {0.f, 0.f}};
#pragma unroll
        for (int mt = 0; mt < 2; mt++)
#pragma unroll
            for (int nt = 0; nt < 4; nt++) {
                int row = m0 + mt * 16 + gid;
                int col = n0 + nt * 8 + tig * 2;
                float* cc = c[mt][nt];
                uint32_t a0 = sb + R1_OFF + (uint32_t)(row * LD2 + col) * 2;
                uint32_t a1 = sb + R1_OFF + (uint32_t)((row + 8) * LD2 + col) * 2;
                uint32_t p0 = lds32(a0), p1 = lds32(a1);
                float s0 = siluf(cc[0] + ubf_lo(p0));
                float s1 = siluf(cc[1] + ubf_hi(p0));
                float s2 = siluf(cc[2] + ubf_lo(p1));
                float s3 = siluf(cc[3] + ubf_hi(p1));
                p[mt][0] += s0 * sWEI[col] + s1 * sWEI[col + 1];
                p[mt][1] += s2 * sWEI[col] + s3 * sWEI[col + 1];
                sts32(a0, pk(s0, s1));
                sts32(a1, pk(s2, s3));
            }
#pragma unroll
        for (int mt = 0; mt < 2; mt++)
#pragma unroll
            for (int hh = 0; hh < 2; hh++) {
                float v = p[mt][hh];
                v += __shfl_xor_sync(0xffffffffu, v, 1);
                v += __shfl_xor_sync(0xffffffffu, v, 2);
                if (tig == 0)
                    sPart[(wid & 3) * 128 + m0 + mt * 16 + hh * 8 + gid] = v;
            }
    }
    __syncthreads();

    if (tid < 128) {
        float t = sPart[tid] + sPart[128 + tid] + sPart[256 + tid] + sPart[384 + tid]
                + g_cei;
        sEij[tid] = 1.f / (1.f + __expf(-t));
    }
    __syncthreads();

    // ---- GEMM2: mij = S @ W2 (+b2); scatter directly from registers ----
    zero_c(c);
    warp_gemm32(sb + R1_OFF + aOff2, sb + RW2_OFF + bOff2, LD2 * 2, 8, c);
#pragma unroll
    for (int mt = 0; mt < 2; mt++) {
        int row = m0 + mt * 16 + gid;
        int d0 = sDst[row], d1 = sDst[row + 8];
        float e0v = sEij[row], e1v = sEij[row + 8];
        float* g0 = g_mi + (size_t)d0 * HIDD;
        float* g1 = g_mi + (size_t)d1 * HIDD;
#pragma unroll
        for (int nt = 0; nt < 4; nt++) {
            int col = n0 + nt * 8 + tig * 2;
            float* cc = c[mt][nt];
            float b0 = sB2[col], b1 = sB2[col + 1];
            asm volatile("red.global.add.v2.f32 [%0], {%1,%2};"
                         :: "l"(g0 + col), "f"((cc[0] + b0) * e0v),
                            "f"((cc[1] + b1) * e0v) : "memory");
            asm volatile("red.global.add.v2.f32 [%0], {%1,%2};"
                         :: "l"(g1 + col), "f"((cc[2] + b0) * e1v),
                            "f"((cc[3] + b1) * e1v) : "memory");
        }
    }
    CPA_WAIT0();
    __syncthreads();   // W23t visible to all

    // ---- GEMM3': u_pre = S @ W23; gate partials ----
    zero_c(c);
    warp_gemm32(sb + R1_OFF + aOff2, sb + RW23_OFF + bOff2, LD2 * 2, 8, c);
    {
        float p[2][2] = {{0.f, 0.f}, {0.f, 0.f}};
#pragma unroll
        for (int mt = 0; mt < 2; mt++)
#pragma unroll
            for (int nt = 0; nt < 4; nt++) {
                int col = n0 + nt * 8 + tig * 2;
                float* cc = c[mt][nt];
                p[mt][0] += siluf(cc[0] + sB23[col]) * sXW2[col]
                          + siluf(cc[1] + sB23[col + 1]) * sXW2[col + 1];
                p[mt][1] += siluf(cc[2] + sB23[col]) * sXW2[col]
                          + siluf(cc[3] + sB23[col + 1]) * sXW2[col + 1];
            }
#pragma unroll
        for (int mt = 0; mt < 2; mt++)
#pragma unroll
            for (int hh = 0; hh < 2; hh++) {
                float v = p[mt][hh];
                v += __shfl_xor_sync(0xffffffffu, v, 1);
                v += __shfl_xor_sync(0xffffffffu, v, 2);
                if (tig == 0)
                    sPart[(wid & 3) * 128 + m0 + mt * 16 + hh * 8 + gid] = v;
            }
    }
    __syncthreads();

    if (tid < 128) {
        float g = tanhf(sPart[tid] + sPart[128 + tid] + sPart[256 + tid] + sPart[384 + tid]);
        float coef = g / (sqrtf(sDsq[tid] + 1e-8f) + 1.f);
        int d = sDst[tid];
        atomicAdd(&x_out[d * 3 + 0], sRlX[tid] * coef);
        atomicAdd(&x_out[d * 3 + 1], sRlY[tid] * coef);
        atomicAdd(&x_out[d * 3 + 2], sRlZ[tid] * coef);
    }
}

// ---------------------------------------------------------------------------
// Node kernel: h_out = h + nm2(silu(mi@nm_w1a + Ph + b1)) + b2
// ---------------------------------------------------------------------------
__global__ void __launch_bounds__(NT, 2) egnn_node_kernel(
    const float* __restrict__ h,
    const float* __restrict__ nm_b1, const float* __restrict__ nm_b2,
    float* __restrict__ h_out)
{
    extern __shared__ unsigned char sm[];
    const uint32_t sb = smem_u32(sm);
    const int tid  = threadIdx.x;
    const int wid  = tid >> 5;
    const int lane = tid & 31;
    const int gid  = lane >> 2;
    const int tig  = lane & 3;
    const int m0   = (wid >> 2) * 32;
    const int n0   = (wid & 3) * 32;
    const int nb   = blockIdx.x * ME;

    float* sB1 = (float*)(sm + 0);
    float* sB2 = (float*)(sm + 512);

    for (int q = tid; q < WBYTES / 16; q += NT)
        cpa16(sb + NW_OFF + q * 16, (const unsigned char*)g_nw1at + q * 16);
    CPA_COMMIT();

    if (tid < 128) { sB1[tid] = nm_b1[tid]; sB2[tid] = nm_b2[tid]; }

    for (int q = tid; q < ME * 16; q += NT) {
        int e = q >> 4, ch = q & 15;
        int n = nb + e;
        uint4 w = make_uint4(0, 0, 0, 0);
        if (n < NN) {
            const float4* sp = (const float4*)(g_mi + (size_t)n * HIDD + ch * 8);
            float4 v0 = sp[0], v1 = sp[1];
            w.x = pk(v0.x, v0.y); w.y = pk(v0.z, v0.w);
            w.z = pk(v1.x, v1.y); w.w = pk(v1.z, v1.w);
        }
        sts128(sb + NA_OFF + (uint32_t)(e * LD2 + ch * 8) * 2, w);
    }
    CPA_WAIT0();
    __syncthreads();

    const uint32_t aOff = (uint32_t)(m0 + (lane & 15)) * (LD2 * 2) + ((lane >> 4) << 4);
    const uint32_t bOff = (uint32_t)(n0 + (lane & 7) + ((lane >> 4) << 3)) * (LD2 * 2)
                        + (((lane >> 3) & 1) << 4);
    float c[2][4][4];

    zero_c(c);
    warp_gemm32(sb + NA_OFF + aOff, sb + NW_OFF + bOff, LD2 * 2, 8, c);
    __syncthreads();

    for (int q = tid; q < WBYTES / 16; q += NT)
        cpa16(sb + NW_OFF + q * 16, (const unsigned char*)g_nw2t + q * 16);
    CPA_COMMIT();

#pragma unroll
    for (int mt = 0; mt < 2; mt++)
#pragma unroll
        for (int nt = 0; nt < 4; nt++) {
            int row = m0 + mt * 16 + gid;
            int col = n0 + nt * 8 + tig * 2;
            float* cc = c[mt][nt];
            int na = nb + row, na2 = nb + row + 8;
            float2 p0 = make_float2(0.f, 0.f), p1 = make_float2(0.f, 0.f);
            if (na < NN)  p0 = *(const float2*)(g_ph + (size_t)na * HIDD + col);
            if (na2 < NN) p1 = *(const float2*)(g_ph + (size_t)na2 * HIDD + col);
            sts32(sb + NA_OFF + (uint32_t)(row * LD2 + col) * 2,
                  pk(siluf(cc[0] + p0.x + sB1[col]), siluf(cc[1] + p0.y + sB1[col + 1])));
            sts32(sb + NA_OFF + (uint32_t)((row + 8) * LD2 + col) * 2,
                  pk(siluf(cc[2] + p1.x + sB1[col]), siluf(cc[3] + p1.y + sB1[col + 1])));
        }
    CPA_WAIT0();
    __syncthreads();

    zero_c(c);
    warp_gemm32(sb + NA_OFF + aOff, sb + NW_OFF + bOff, LD2 * 2, 8, c);

#pragma unroll
    for (int mt = 0; mt < 2; mt++)
#pragma unroll
        for (int nt = 0; nt < 4; nt++) {
            int row = m0 + mt * 16 + gid;
            int col = n0 + nt * 8 + tig * 2;
            float* cc = c[mt][nt];
            int na = nb + row, na2 = nb + row + 8;
            if (na < NN) {
                const float2 hv = *(const float2*)(h + (size_t)na * HIDD + col);
                *(float2*)(h_out + (size_t)na * HIDD + col) =
                    make_float2(cc[0] + sB2[col] + hv.x, cc[1] + sB2[col + 1] + hv.y);
            }
            if (na2 < NN) {
                const float2 hv = *(const float2*)(h + (size_t)na2 * HIDD + col);
                *(float2*)(h_out + (size_t)na2 * HIDD + col) =
                    make_float2(cc[2] + sB2[col] + hv.x, cc[3] + sB2[col + 1] + hv.y);
            }
        }
}

// ---------------------------------------------------------------------------
extern "C" void kernel_launch(void* const* d_in, const int* in_sizes, int n_in,
                              void* d_out, int out_size) {
    const float* h     = (const float*)d_in[0];
    const float* x     = (const float*)d_in[1];
    const int*   eidx  = (const int*)  d_in[2];
    const float* eattr = (const float*)d_in[3];
    const float* em_w1 = (const float*)d_in[4];
    const float* em_b1 = (const float*)d_in[5];
    const float* em_w2 = (const float*)d_in[6];
    const float* em_b2 = (const float*)d_in[7];
    const float* ei_w  = (const float*)d_in[8];
    const float* ei_b  = (const float*)d_in[9];
    const float* xm_w1 = (const float*)d_in[10];
    const float* xm_b1 = (const float*)d_in[11];
    const float* xm_w2 = (const float*)d_in[12];
    const float* nm_w1 = (const float*)d_in[13];
    const float* nm_b1 = (const float*)d_in[14];
    const float* nm_w2 = (const float*)d_in[15];
    const float* nm_b2 = (const float*)d_in[16];

    float* out   = (float*)d_out;
    float* h_out = out;                        // [NN, 128]
    float* x_out = out + (size_t)NN * HIDD;    // [NN, 3]

    cudaFuncSetAttribute(egnn_edge_kernel,
                         cudaFuncAttributeMaxDynamicSharedMemorySize, EDGE_SMEM);
    cudaFuncSetAttribute(egnn_node_kernel,
                         cudaFuncAttributeMaxDynamicSharedMemorySize, NODE_SMEM);
    cudaFuncSetAttribute(egnn_pre_kernel,
                         cudaFuncAttributeMaxDynamicSharedMemorySize, NODE_SMEM);

    egnn_init_kernel<<<1024, 256>>>(x, x_out);
    egnn_prep_kernel<<<256, 256>>>(em_w1, em_w2, xm_w1, nm_w1, nm_w2,
                                   em_b1, em_b2, ei_w, ei_b, xm_b1);
    egnn_pre_kernel<<<(NN + ME - 1) / ME, NT, NODE_SMEM>>>(h);
    egnn_edge_kernel<<<NE / ME, NT, EDGE_SMEM>>>(
        x, eidx, eattr, em_b2, xm_w2, x_out);
    egnn_node_kernel<<<(NN + ME - 1) / ME, NT, NODE_SMEM>>>(
        h, nm_b1, nm_b2, h_out);
}